// round 2
// baseline (speedup 1.0000x reference)
#include <cuda_runtime.h>
#include <math.h>

// Problem constants
#define BB   2
#define SS   2048
#define DD   2048
#define HH   16
#define DK   128
#define MTOK (BB * SS)          // 4096 tokens
#define SCALE 0.08838834764831845f  // 1/sqrt(128)

// Scratch (device globals; no cudaMalloc allowed)
static __device__ float g_q[(size_t)MTOK * DD];
static __device__ float g_k[(size_t)MTOK * DD];
static __device__ float g_v[(size_t)MTOK * DD];
static __device__ float g_x[(size_t)MTOK * DD];

// ---------------------------------------------------------------------------
// Generic C = A @ W^T + bias.  A:[M,K] row-major, W:[N,K] row-major, C:[M,N].
// 128x128 block, BK=8, 256 threads, 8x8 microtile (split 4+4 register mapping).
// ---------------------------------------------------------------------------
#define BM 128
#define BN 128
#define BK 8

__global__ __launch_bounds__(256) void sgemm_xwT(
    const float* __restrict__ A, const float* __restrict__ W,
    const float* __restrict__ bias, float* __restrict__ C,
    int M, int N, int K)
{
    __shared__ float As[BK][BM + 4];
    __shared__ float Bs[BK][BN + 4];

    const int tid = threadIdx.x;
    const int bn = blockIdx.x;
    const int bm = blockIdx.y;

    const int lrow = tid >> 1;          // 0..127
    const int lcol = (tid & 1) * 4;     // 0 or 4

    const float* Ag = A + (size_t)(bm * BM + lrow) * K + lcol;
    const float* Bg = W + (size_t)(bn * BN + lrow) * K + lcol;

    const int tx = tid & 15;            // 0..15
    const int ty = tid >> 4;            // 0..15

    float acc[8][8];
    #pragma unroll
    for (int i = 0; i < 8; i++)
        #pragma unroll
        for (int j = 0; j < 8; j++) acc[i][j] = 0.0f;

    for (int k0 = 0; k0 < K; k0 += BK) {
        float4 a4 = *(const float4*)(Ag + k0);
        float4 b4 = *(const float4*)(Bg + k0);
        As[lcol + 0][lrow] = a4.x; As[lcol + 1][lrow] = a4.y;
        As[lcol + 2][lrow] = a4.z; As[lcol + 3][lrow] = a4.w;
        Bs[lcol + 0][lrow] = b4.x; Bs[lcol + 1][lrow] = b4.y;
        Bs[lcol + 2][lrow] = b4.z; Bs[lcol + 3][lrow] = b4.w;
        __syncthreads();

        #pragma unroll
        for (int k = 0; k < BK; k++) {
            float ar[8], br[8];
            *(float4*)&ar[0] = *(const float4*)&As[k][ty * 4];
            *(float4*)&ar[4] = *(const float4*)&As[k][64 + ty * 4];
            *(float4*)&br[0] = *(const float4*)&Bs[k][tx * 4];
            *(float4*)&br[4] = *(const float4*)&Bs[k][64 + tx * 4];
            #pragma unroll
            for (int i = 0; i < 8; i++)
                #pragma unroll
                for (int j = 0; j < 8; j++)
                    acc[i][j] += ar[i] * br[j];
        }
        __syncthreads();
    }

    // Epilogue: add bias, write
    #pragma unroll
    for (int ih = 0; ih < 2; ih++) {
        #pragma unroll
        for (int ii = 0; ii < 4; ii++) {
            int i = ih * 4 + ii;
            int grow = bm * BM + ih * 64 + ty * 4 + ii;
            #pragma unroll
            for (int jh = 0; jh < 2; jh++) {
                int gcol = bn * BN + jh * 64 + tx * 4;
                float4 v4;
                v4.x = acc[i][jh * 4 + 0] + bias[gcol + 0];
                v4.y = acc[i][jh * 4 + 1] + bias[gcol + 1];
                v4.z = acc[i][jh * 4 + 2] + bias[gcol + 2];
                v4.w = acc[i][jh * 4 + 3] + bias[gcol + 3];
                *(float4*)(C + (size_t)grow * N + gcol) = v4;
            }
        }
    }
}

// ---------------------------------------------------------------------------
// Scores: scores[bh, i, j] = (q_i . k_j) * SCALE, lower-triangular tiles only.
// q/k stored as [token, D] with head slice at column h*DK.  K-reduction = 128.
// ---------------------------------------------------------------------------
__global__ __launch_bounds__(256) void scores_kernel(
    const float* __restrict__ q, const float* __restrict__ k,
    float* __restrict__ attn)
{
    const int bn = blockIdx.x;
    const int bm = blockIdx.y;
    if (bn > bm) return;                 // fully masked tile
    const int bh = blockIdx.z;
    const int b  = bh / HH;
    const int h  = bh % HH;

    __shared__ float As[BK][BM + 4];
    __shared__ float Bs[BK][BN + 4];

    const int tid  = threadIdx.x;
    const int lrow = tid >> 1;
    const int lcol = (tid & 1) * 4;
    const int tx = tid & 15;
    const int ty = tid >> 4;

    const float* Ag = q + (size_t)(b * SS + bm * BM + lrow) * DD + h * DK + lcol;
    const float* Bg = k + (size_t)(b * SS + bn * BN + lrow) * DD + h * DK + lcol;
    float* out = attn + (size_t)bh * SS * SS;

    float acc[8][8];
    #pragma unroll
    for (int i = 0; i < 8; i++)
        #pragma unroll
        for (int j = 0; j < 8; j++) acc[i][j] = 0.0f;

    #pragma unroll 1
    for (int k0 = 0; k0 < DK; k0 += BK) {
        float4 a4 = *(const float4*)(Ag + k0);
        float4 b4 = *(const float4*)(Bg + k0);
        As[lcol + 0][lrow] = a4.x; As[lcol + 1][lrow] = a4.y;
        As[lcol + 2][lrow] = a4.z; As[lcol + 3][lrow] = a4.w;
        Bs[lcol + 0][lrow] = b4.x; Bs[lcol + 1][lrow] = b4.y;
        Bs[lcol + 2][lrow] = b4.z; Bs[lcol + 3][lrow] = b4.w;
        __syncthreads();

        #pragma unroll
        for (int kk = 0; kk < BK; kk++) {
            float ar[8], br[8];
            *(float4*)&ar[0] = *(const float4*)&As[kk][ty * 4];
            *(float4*)&ar[4] = *(const float4*)&As[kk][64 + ty * 4];
            *(float4*)&br[0] = *(const float4*)&Bs[kk][tx * 4];
            *(float4*)&br[4] = *(const float4*)&Bs[kk][64 + tx * 4];
            #pragma unroll
            for (int i = 0; i < 8; i++)
                #pragma unroll
                for (int j = 0; j < 8; j++)
                    acc[i][j] += ar[i] * br[j];
        }
        __syncthreads();
    }

    #pragma unroll
    for (int ih = 0; ih < 2; ih++) {
        #pragma unroll
        for (int ii = 0; ii < 4; ii++) {
            int i = ih * 4 + ii;
            int grow = bm * BM + ih * 64 + ty * 4 + ii;
            #pragma unroll
            for (int jh = 0; jh < 2; jh++) {
                int gcol = bn * BN + jh * 64 + tx * 4;
                float4 v4;
                v4.x = acc[i][jh * 4 + 0] * SCALE;
                v4.y = acc[i][jh * 4 + 1] * SCALE;
                v4.z = acc[i][jh * 4 + 2] * SCALE;
                v4.w = acc[i][jh * 4 + 3] * SCALE;
                *(float4*)(out + (size_t)grow * SS + gcol) = v4;
            }
        }
    }
}

// ---------------------------------------------------------------------------
// In-place causal softmax. One block per (bh, s) row. Row held in registers
// (2048/256 = 8 per thread). Masked tail written as exact 0 (matches exp(-1e9)
// underflow in the reference).
// ---------------------------------------------------------------------------
__global__ __launch_bounds__(256) void softmax_causal(float* __restrict__ attn)
{
    const int blk = blockIdx.x;           // bh * SS + s
    const int s   = blk & (SS - 1);
    float* row = attn + (size_t)blk * SS;
    const int tid = threadIdx.x;
    const int valid = s + 1;

    __shared__ float red[256];

    float x[8];
    float m = -3.4e38f;
    #pragma unroll
    for (int i = 0; i < 8; i++) {
        int j = tid + i * 256;
        x[i] = (j < valid) ? row[j] : -3.4e38f;
        m = fmaxf(m, x[i]);
    }
    red[tid] = m;
    __syncthreads();
    for (int o = 128; o > 0; o >>= 1) {
        if (tid < o) red[tid] = fmaxf(red[tid], red[tid + o]);
        __syncthreads();
    }
    m = red[0];
    __syncthreads();

    float sum = 0.0f;
    #pragma unroll
    for (int i = 0; i < 8; i++) {
        int j = tid + i * 256;
        if (j < valid) { x[i] = __expf(x[i] - m); sum += x[i]; }
        else x[i] = 0.0f;
    }
    red[tid] = sum;
    __syncthreads();
    for (int o = 128; o > 0; o >>= 1) {
        if (tid < o) red[tid] += red[tid + o];
        __syncthreads();
    }
    const float inv = 1.0f / red[0];

    #pragma unroll
    for (int i = 0; i < 8; i++) {
        int j = tid + i * 256;
        row[j] = x[i] * inv;
    }
}

// ---------------------------------------------------------------------------
// x = attn @ v per (b,h). M=2048, N=128(DK), K truncated at diagonal block.
// attn rows are dense-with-zero-tail, so K-loop up to (bm+1)*BM is exact.
// ---------------------------------------------------------------------------
__global__ __launch_bounds__(256) void av_kernel(
    const float* __restrict__ attn, const float* __restrict__ v,
    float* __restrict__ x)
{
    const int bm = blockIdx.y;
    const int bh = blockIdx.z;
    const int b  = bh / HH;
    const int h  = bh % HH;

    __shared__ float As[BK][BM + 4];
    __shared__ float Bs[BK][DK + 4];

    const int tid  = threadIdx.x;
    const int lrow = tid >> 1;
    const int lcol = (tid & 1) * 4;
    const int vrow = tid >> 5;           // 0..7 (k within tile)
    const int vcol = (tid & 31) * 4;     // 0..124
    const int tx = tid & 15;
    const int ty = tid >> 4;

    const float* Ag = attn + (size_t)bh * SS * SS + (size_t)(bm * BM + lrow) * SS + lcol;
    const float* Vg = v + (size_t)b * SS * DD + h * DK + vcol;

    float acc[8][8];
    #pragma unroll
    for (int i = 0; i < 8; i++)
        #pragma unroll
        for (int j = 0; j < 8; j++) acc[i][j] = 0.0f;

    const int kmax = (bm + 1) * BM;
    for (int k0 = 0; k0 < kmax; k0 += BK) {
        float4 a4 = *(const float4*)(Ag + k0);
        As[lcol + 0][lrow] = a4.x; As[lcol + 1][lrow] = a4.y;
        As[lcol + 2][lrow] = a4.z; As[lcol + 3][lrow] = a4.w;
        float4 b4 = *(const float4*)(Vg + (size_t)(k0 + vrow) * DD);
        *(float4*)&Bs[vrow][vcol] = b4;
        __syncthreads();

        #pragma unroll
        for (int kk = 0; kk < BK; kk++) {
            float ar[8], br[8];
            *(float4*)&ar[0] = *(const float4*)&As[kk][ty * 4];
            *(float4*)&ar[4] = *(const float4*)&As[kk][64 + ty * 4];
            *(float4*)&br[0] = *(const float4*)&Bs[kk][tx * 4];
            *(float4*)&br[4] = *(const float4*)&Bs[kk][64 + tx * 4];
            #pragma unroll
            for (int i = 0; i < 8; i++)
                #pragma unroll
                for (int j = 0; j < 8; j++)
                    acc[i][j] += ar[i] * br[j];
        }
        __syncthreads();
    }

    #pragma unroll
    for (int ih = 0; ih < 2; ih++) {
        #pragma unroll
        for (int ii = 0; ii < 4; ii++) {
            int i = ih * 4 + ii;
            int grow = bm * BM + ih * 64 + ty * 4 + ii;
            #pragma unroll
            for (int jh = 0; jh < 2; jh++) {
                int gcol = jh * 64 + tx * 4;
                float4 v4;
                v4.x = acc[i][jh * 4 + 0];
                v4.y = acc[i][jh * 4 + 1];
                v4.z = acc[i][jh * 4 + 2];
                v4.w = acc[i][jh * 4 + 3];
                *(float4*)(x + (size_t)(b * SS + grow) * DD + h * DK + gcol) = v4;
            }
        }
    }
}

// ---------------------------------------------------------------------------
extern "C" void kernel_launch(void* const* d_in, const int* in_sizes, int n_in,
                              void* d_out, int out_size)
{
    const float* query = (const float*)d_in[0];
    const float* key   = (const float*)d_in[1];
    const float* value = (const float*)d_in[2];
    const float* Wq = (const float*)d_in[3];
    const float* bq = (const float*)d_in[4];
    const float* Wk = (const float*)d_in[5];
    const float* bk = (const float*)d_in[6];
    const float* Wv = (const float*)d_in[7];
    const float* bv = (const float*)d_in[8];
    const float* Wo = (const float*)d_in[9];
    const float* bo = (const float*)d_in[10];

    float* out  = (float*)d_out;                       // [4096, 2048]
    float* attn = out + (size_t)MTOK * DD;             // [32, 2048, 2048]

    float *q, *k, *v, *x;
    cudaGetSymbolAddress((void**)&q, g_q);
    cudaGetSymbolAddress((void**)&k, g_k);
    cudaGetSymbolAddress((void**)&v, g_v);
    cudaGetSymbolAddress((void**)&x, g_x);

    dim3 gproj(DD / BN, MTOK / BM);                    // (16, 32)
    sgemm_xwT<<<gproj, 256>>>(query, Wq, bq, q, MTOK, DD, DD);
    sgemm_xwT<<<gproj, 256>>>(key,   Wk, bk, k, MTOK, DD, DD);
    sgemm_xwT<<<gproj, 256>>>(value, Wv, bv, v, MTOK, DD, DD);

    dim3 gsc(SS / BN, SS / BM, BB * HH);               // (16, 16, 32)
    scores_kernel<<<gsc, 256>>>(q, k, attn);

    softmax_causal<<<BB * HH * SS, 256>>>(attn);

    dim3 gav(1, SS / BM, BB * HH);                     // (1, 16, 32)
    av_kernel<<<gav, 256>>>(attn, v, x);

    sgemm_xwT<<<gproj, 256>>>(x, Wo, bo, out, MTOK, DD, DD);
}

// round 4
// speedup vs baseline: 1.5609x; 1.5609x over previous
#include <cuda_runtime.h>
#include <cuda_bf16.h>
#include <cstdint>
#include <math.h>

// ---------------------------------------------------------------------------
// Problem constants
// ---------------------------------------------------------------------------
#define BB   2
#define SS   2048
#define DD   2048
#define HH   16
#define DK   128
#define MTOK (BB * SS)          // 4096 tokens
#define SCALE 0.08838834764831845f  // 1/sqrt(128)

// Scratch (device globals; no cudaMalloc allowed)
static __device__ float g_q[(size_t)MTOK * DD];
static __device__ float g_k[(size_t)MTOK * DD];
static __device__ float g_v[(size_t)MTOK * DD];
static __device__ float g_x[(size_t)MTOK * DD];

// ---------------------------------------------------------------------------
// mma.sync helpers (plain sm_80+ PTX: legal on base compute_103 target)
// ---------------------------------------------------------------------------
#define LDSM_X4(r0, r1, r2, r3, addr) \
    asm volatile("ldmatrix.sync.aligned.m8n8.x4.shared.b16 {%0,%1,%2,%3}, [%4];" \
        : "=r"(r0), "=r"(r1), "=r"(r2), "=r"(r3) : "r"(addr))

#define MMA16816(c, a0, a1, a2, a3, b0, b1) \
    asm volatile("mma.sync.aligned.m16n8k16.row.col.f32.bf16.bf16.f32 " \
        "{%0,%1,%2,%3}, {%4,%5,%6,%7}, {%8,%9}, {%0,%1,%2,%3};" \
        : "+f"((c)[0]), "+f"((c)[1]), "+f"((c)[2]), "+f"((c)[3]) \
        : "r"(a0), "r"(a1), "r"(a2), "r"(a3), "r"(b0), "r"(b1))

__device__ __forceinline__ uint32_t smem_u32(const void* p) {
    uint32_t a;
    asm("{ .reg .u64 t; cvta.to.shared.u64 t, %1; cvt.u32.u64 %0, t; }"
        : "=r"(a) : "l"(p));
    return a;
}

__device__ __forceinline__ uint32_t pack_bf2(__nv_bfloat16 a, __nv_bfloat16 b) {
    return (uint32_t)__bfloat16_as_ushort(a) |
           ((uint32_t)__bfloat16_as_ushort(b) << 16);
}

// Split a float4 into bf16 hi and lo planes (packed as uint2 each)
__device__ __forceinline__ void split4(const float4 f, uint2& hi, uint2& lo) {
    __nv_bfloat16 h0 = __float2bfloat16_rn(f.x);
    __nv_bfloat16 h1 = __float2bfloat16_rn(f.y);
    __nv_bfloat16 h2 = __float2bfloat16_rn(f.z);
    __nv_bfloat16 h3 = __float2bfloat16_rn(f.w);
    __nv_bfloat16 l0 = __float2bfloat16_rn(f.x - __bfloat162float(h0));
    __nv_bfloat16 l1 = __float2bfloat16_rn(f.y - __bfloat162float(h1));
    __nv_bfloat16 l2 = __float2bfloat16_rn(f.z - __bfloat162float(h2));
    __nv_bfloat16 l3 = __float2bfloat16_rn(f.w - __bfloat162float(h3));
    hi.x = pack_bf2(h0, h1); hi.y = pack_bf2(h2, h3);
    lo.x = pack_bf2(l0, l1); lo.y = pack_bf2(l2, l3);
}

// ---------------------------------------------------------------------------
// bf16 split-2 tensor-core GEMM: C = A @ W^T + bias.
// A:[M,K] row-major, W:[N,K] row-major (both K contiguous -> mma row.col).
// Tile 128x128x32. 256 threads = 8 warps, each computing 64x32.
// smem: 4 bf16 planes (Ahi, Alo, Bhi, Blo), 128 rows x 32 elems,
//       row stride 40 elems (80B) -> conflict-free ldmatrix.
// ---------------------------------------------------------------------------
#define GK 2048
#define RSTRIDE 80                      // bytes per smem row
#define PL_AHI 0
#define PL_ALO 10240
#define PL_BHI 20480
#define PL_BLO 30720

__global__ __launch_bounds__(256) void gemm_mma_xwT(
    const float* __restrict__ A, const float* __restrict__ W,
    const float* __restrict__ bias, float* __restrict__ C)
{
    __shared__ __align__(16) char sm[40960];
    const uint32_t sbase = smem_u32(sm);

    const int tid  = threadIdx.x;
    const int lane = tid & 31;
    const int wid  = tid >> 5;
    const int wm   = wid >> 2;          // 0..1 (64-row half)
    const int wn   = wid & 3;           // 0..3 (32-col quarter)
    const int bn   = blockIdx.x;
    const int bm   = blockIdx.y;

    // Global load map: 8 k-quads (float4) x 32 row-groups; each thread does
    // 4 rows (r, r+32, r+64, r+96) for both A and B.
    const int kq    = tid & 7;          // float4 index within 32-float chunk
    const int rbase = tid >> 3;         // 0..31
    const float* Ag = A + (size_t)(bm * 128 + rbase) * GK + kq * 4;
    const float* Bg = W + (size_t)(bn * 128 + rbase) * GK + kq * 4;

    float acc[4][4][4];
    #pragma unroll
    for (int i = 0; i < 4; i++)
        #pragma unroll
        for (int j = 0; j < 4; j++)
            #pragma unroll
            for (int c = 0; c < 4; c++) acc[i][j][c] = 0.0f;

    // ldmatrix per-lane smem addresses (byte offsets from sbase)
    const uint32_t aAddr = sbase + PL_AHI
        + (uint32_t)(wm * 64 + (lane & 15)) * RSTRIDE + (lane >> 4) * 16;
    const uint32_t bAddr = sbase + PL_BHI
        + (uint32_t)(wn * 32 + (lane & 7) + ((lane >> 4) & 1) * 8) * RSTRIDE
        + ((lane >> 3) & 1) * 16;

    // --- prologue: load tile 0, store to smem ---
    float4 aS[4], bS[4];
    #pragma unroll
    for (int p = 0; p < 4; p++) {
        aS[p] = *(const float4*)(Ag + (size_t)(p * 32) * GK);
        bS[p] = *(const float4*)(Bg + (size_t)(p * 32) * GK);
    }
    #pragma unroll
    for (int p = 0; p < 4; p++) {
        const uint32_t off = (uint32_t)(rbase + p * 32) * RSTRIDE + kq * 8;
        uint2 hi, lo;
        split4(aS[p], hi, lo);
        *(uint2*)(sm + PL_AHI + off) = hi;
        *(uint2*)(sm + PL_ALO + off) = lo;
        split4(bS[p], hi, lo);
        *(uint2*)(sm + PL_BHI + off) = hi;
        *(uint2*)(sm + PL_BLO + off) = lo;
    }
    __syncthreads();

    const int nIter = GK / 32;          // 64
    for (int s = 0; s < nIter; s++) {
        // prefetch next tile into registers (latency hides under MMAs)
        if (s + 1 < nIter) {
            const int k0 = (s + 1) * 32;
            #pragma unroll
            for (int p = 0; p < 4; p++) {
                aS[p] = *(const float4*)(Ag + (size_t)(p * 32) * GK + k0);
                bS[p] = *(const float4*)(Bg + (size_t)(p * 32) * GK + k0);
            }
        }

        // compute on current smem tile: 2 k-steps of 16
        #pragma unroll
        for (int kk = 0; kk < 2; kk++) {
            uint32_t ahi[4][4], alo[4][4];
            uint32_t bhi[2][4], blo[2][4];
            #pragma unroll
            for (int mt = 0; mt < 4; mt++) {
                const uint32_t a = aAddr + mt * (16 * RSTRIDE) + kk * 32;
                LDSM_X4(ahi[mt][0], ahi[mt][1], ahi[mt][2], ahi[mt][3], a);
                LDSM_X4(alo[mt][0], alo[mt][1], alo[mt][2], alo[mt][3],
                        a + (PL_ALO - PL_AHI));
            }
            #pragma unroll
            for (int pp = 0; pp < 2; pp++) {
                const uint32_t b = bAddr + pp * (16 * RSTRIDE) + kk * 32;
                LDSM_X4(bhi[pp][0], bhi[pp][1], bhi[pp][2], bhi[pp][3], b);
                LDSM_X4(blo[pp][0], blo[pp][1], blo[pp][2], blo[pp][3],
                        b + (PL_BLO - PL_BHI));
            }
            #pragma unroll
            for (int mt = 0; mt < 4; mt++) {
                #pragma unroll
                for (int pp = 0; pp < 2; pp++) {
                    #pragma unroll
                    for (int t = 0; t < 2; t++) {
                        const int nt = pp * 2 + t;
                        MMA16816(acc[mt][nt],
                                 ahi[mt][0], ahi[mt][1], ahi[mt][2], ahi[mt][3],
                                 bhi[pp][t * 2], bhi[pp][t * 2 + 1]);
                        MMA16816(acc[mt][nt],
                                 ahi[mt][0], ahi[mt][1], ahi[mt][2], ahi[mt][3],
                                 blo[pp][t * 2], blo[pp][t * 2 + 1]);
                        MMA16816(acc[mt][nt],
                                 alo[mt][0], alo[mt][1], alo[mt][2], alo[mt][3],
                                 bhi[pp][t * 2], bhi[pp][t * 2 + 1]);
                    }
                }
            }
        }
        __syncthreads();

        // store prefetched tile
        if (s + 1 < nIter) {
            #pragma unroll
            for (int p = 0; p < 4; p++) {
                const uint32_t off = (uint32_t)(rbase + p * 32) * RSTRIDE + kq * 8;
                uint2 hi, lo;
                split4(aS[p], hi, lo);
                *(uint2*)(sm + PL_AHI + off) = hi;
                *(uint2*)(sm + PL_ALO + off) = lo;
                split4(bS[p], hi, lo);
                *(uint2*)(sm + PL_BHI + off) = hi;
                *(uint2*)(sm + PL_BLO + off) = lo;
            }
            __syncthreads();
        }
    }

    // --- epilogue: acc + bias -> C ---
    #pragma unroll
    for (int mt = 0; mt < 4; mt++) {
        const int row = bm * 128 + wm * 64 + mt * 16 + (lane >> 2);
        #pragma unroll
        for (int nt = 0; nt < 4; nt++) {
            const int col = bn * 128 + wn * 32 + nt * 8 + (lane & 3) * 2;
            const float b0 = bias[col], b1 = bias[col + 1];
            float2 o0, o1;
            o0.x = acc[mt][nt][0] + b0; o0.y = acc[mt][nt][1] + b1;
            o1.x = acc[mt][nt][2] + b0; o1.y = acc[mt][nt][3] + b1;
            *(float2*)(C + (size_t)row * DD + col) = o0;
            *(float2*)(C + (size_t)(row + 8) * DD + col) = o1;
        }
    }
}

// ---------------------------------------------------------------------------
// Scores: scores[bh, i, j] = (q_i . k_j) * SCALE, lower-triangular tiles only.
// ---------------------------------------------------------------------------
#define BM 128
#define BN 128
#define BK 8

__global__ __launch_bounds__(256) void scores_kernel(
    const float* __restrict__ q, const float* __restrict__ k,
    float* __restrict__ attn)
{
    const int bn = blockIdx.x;
    const int bm = blockIdx.y;
    if (bn > bm) return;                 // fully masked tile
    const int bh = blockIdx.z;
    const int b  = bh / HH;
    const int h  = bh % HH;

    __shared__ float As[BK][BM + 4];
    __shared__ float Bs[BK][BN + 4];

    const int tid  = threadIdx.x;
    const int lrow = tid >> 1;
    const int lcol = (tid & 1) * 4;
    const int tx = tid & 15;
    const int ty = tid >> 4;

    const float* Ag = q + (size_t)(b * SS + bm * BM + lrow) * DD + h * DK + lcol;
    const float* Bg = k + (size_t)(b * SS + bn * BN + lrow) * DD + h * DK + lcol;
    float* out = attn + (size_t)bh * SS * SS;

    float acc[8][8];
    #pragma unroll
    for (int i = 0; i < 8; i++)
        #pragma unroll
        for (int j = 0; j < 8; j++) acc[i][j] = 0.0f;

    #pragma unroll 1
    for (int k0 = 0; k0 < DK; k0 += BK) {
        float4 a4 = *(const float4*)(Ag + k0);
        float4 b4 = *(const float4*)(Bg + k0);
        As[lcol + 0][lrow] = a4.x; As[lcol + 1][lrow] = a4.y;
        As[lcol + 2][lrow] = a4.z; As[lcol + 3][lrow] = a4.w;
        Bs[lcol + 0][lrow] = b4.x; Bs[lcol + 1][lrow] = b4.y;
        Bs[lcol + 2][lrow] = b4.z; Bs[lcol + 3][lrow] = b4.w;
        __syncthreads();

        #pragma unroll
        for (int kk = 0; kk < BK; kk++) {
            float ar[8], br[8];
            *(float4*)&ar[0] = *(const float4*)&As[kk][ty * 4];
            *(float4*)&ar[4] = *(const float4*)&As[kk][64 + ty * 4];
            *(float4*)&br[0] = *(const float4*)&Bs[kk][tx * 4];
            *(float4*)&br[4] = *(const float4*)&Bs[kk][64 + tx * 4];
            #pragma unroll
            for (int i = 0; i < 8; i++)
                #pragma unroll
                for (int j = 0; j < 8; j++)
                    acc[i][j] += ar[i] * br[j];
        }
        __syncthreads();
    }

    #pragma unroll
    for (int ih = 0; ih < 2; ih++) {
        #pragma unroll
        for (int ii = 0; ii < 4; ii++) {
            int i = ih * 4 + ii;
            int grow = bm * BM + ih * 64 + ty * 4 + ii;
            #pragma unroll
            for (int jh = 0; jh < 2; jh++) {
                int gcol = bn * BN + jh * 64 + tx * 4;
                float4 v4;
                v4.x = acc[i][jh * 4 + 0] * SCALE;
                v4.y = acc[i][jh * 4 + 1] * SCALE;
                v4.z = acc[i][jh * 4 + 2] * SCALE;
                v4.w = acc[i][jh * 4 + 3] * SCALE;
                *(float4*)(out + (size_t)grow * SS + gcol) = v4;
            }
        }
    }
}

// ---------------------------------------------------------------------------
// In-place causal softmax. One block per (bh, s) row.
// ---------------------------------------------------------------------------
__global__ __launch_bounds__(256) void softmax_causal(float* __restrict__ attn)
{
    const int blk = blockIdx.x;           // bh * SS + s
    const int s   = blk & (SS - 1);
    float* row = attn + (size_t)blk * SS;
    const int tid = threadIdx.x;
    const int valid = s + 1;

    __shared__ float red[256];

    float x[8];
    float m = -3.4e38f;
    #pragma unroll
    for (int i = 0; i < 8; i++) {
        int j = tid + i * 256;
        x[i] = (j < valid) ? row[j] : -3.4e38f;
        m = fmaxf(m, x[i]);
    }
    red[tid] = m;
    __syncthreads();
    for (int o = 128; o > 0; o >>= 1) {
        if (tid < o) red[tid] = fmaxf(red[tid], red[tid + o]);
        __syncthreads();
    }
    m = red[0];
    __syncthreads();

    float sum = 0.0f;
    #pragma unroll
    for (int i = 0; i < 8; i++) {
        int j = tid + i * 256;
        if (j < valid) { x[i] = __expf(x[i] - m); sum += x[i]; }
        else x[i] = 0.0f;
    }
    red[tid] = sum;
    __syncthreads();
    for (int o = 128; o > 0; o >>= 1) {
        if (tid < o) red[tid] += red[tid + o];
        __syncthreads();
    }
    const float inv = 1.0f / red[0];

    #pragma unroll
    for (int i = 0; i < 8; i++) {
        int j = tid + i * 256;
        row[j] = x[i] * inv;
    }
}

// ---------------------------------------------------------------------------
// x = attn @ v per (b,h). K truncated at diagonal block.
// ---------------------------------------------------------------------------
__global__ __launch_bounds__(256) void av_kernel(
    const float* __restrict__ attn, const float* __restrict__ v,
    float* __restrict__ x)
{
    const int bm = blockIdx.y;
    const int bh = blockIdx.z;
    const int b  = bh / HH;
    const int h  = bh % HH;

    __shared__ float As[BK][BM + 4];
    __shared__ float Bs[BK][DK + 4];

    const int tid  = threadIdx.x;
    const int lrow = tid >> 1;
    const int lcol = (tid & 1) * 4;
    const int vrow = tid >> 5;           // 0..7 (k within tile)
    const int vcol = (tid & 31) * 4;     // 0..124
    const int tx = tid & 15;
    const int ty = tid >> 4;

    const float* Ag = attn + (size_t)bh * SS * SS + (size_t)(bm * BM + lrow) * SS + lcol;
    const float* Vg = v + (size_t)b * SS * DD + h * DK + vcol;

    float acc[8][8];
    #pragma unroll
    for (int i = 0; i < 8; i++)
        #pragma unroll
        for (int j = 0; j < 8; j++) acc[i][j] = 0.0f;

    const int kmax = (bm + 1) * BM;
    for (int k0 = 0; k0 < kmax; k0 += BK) {
        float4 a4 = *(const float4*)(Ag + k0);
        As[lcol + 0][lrow] = a4.x; As[lcol + 1][lrow] = a4.y;
        As[lcol + 2][lrow] = a4.z; As[lcol + 3][lrow] = a4.w;
        float4 b4 = *(const float4*)(Vg + (size_t)(k0 + vrow) * DD);
        *(float4*)&Bs[vrow][vcol] = b4;
        __syncthreads();

        #pragma unroll
        for (int kk = 0; kk < BK; kk++) {
            float ar[8], br[8];
            *(float4*)&ar[0] = *(const float4*)&As[kk][ty * 4];
            *(float4*)&ar[4] = *(const float4*)&As[kk][64 + ty * 4];
            *(float4*)&br[0] = *(const float4*)&Bs[kk][tx * 4];
            *(float4*)&br[4] = *(const float4*)&Bs[kk][64 + tx * 4];
            #pragma unroll
            for (int i = 0; i < 8; i++)
                #pragma unroll
                for (int j = 0; j < 8; j++)
                    acc[i][j] += ar[i] * br[j];
        }
        __syncthreads();
    }

    #pragma unroll
    for (int ih = 0; ih < 2; ih++) {
        #pragma unroll
        for (int ii = 0; ii < 4; ii++) {
            int i = ih * 4 + ii;
            int grow = bm * BM + ih * 64 + ty * 4 + ii;
            #pragma unroll
            for (int jh = 0; jh < 2; jh++) {
                int gcol = jh * 64 + tx * 4;
                float4 v4;
                v4.x = acc[i][jh * 4 + 0];
                v4.y = acc[i][jh * 4 + 1];
                v4.z = acc[i][jh * 4 + 2];
                v4.w = acc[i][jh * 4 + 3];
                *(float4*)(x + (size_t)(b * SS + grow) * DD + h * DK + gcol) = v4;
            }
        }
    }
}

// ---------------------------------------------------------------------------
extern "C" void kernel_launch(void* const* d_in, const int* in_sizes, int n_in,
                              void* d_out, int out_size)
{
    const float* query = (const float*)d_in[0];
    const float* key   = (const float*)d_in[1];
    const float* value = (const float*)d_in[2];
    const float* Wq = (const float*)d_in[3];
    const float* bq = (const float*)d_in[4];
    const float* Wk = (const float*)d_in[5];
    const float* bk = (const float*)d_in[6];
    const float* Wv = (const float*)d_in[7];
    const float* bv = (const float*)d_in[8];
    const float* Wo = (const float*)d_in[9];
    const float* bo = (const float*)d_in[10];

    float* out  = (float*)d_out;                       // [4096, 2048]
    float* attn = out + (size_t)MTOK * DD;             // [32, 2048, 2048]

    float *q, *k, *v, *x;
    cudaGetSymbolAddress((void**)&q, g_q);
    cudaGetSymbolAddress((void**)&k, g_k);
    cudaGetSymbolAddress((void**)&v, g_v);
    cudaGetSymbolAddress((void**)&x, g_x);

    dim3 gproj(DD / 128, MTOK / 128);                  // (16, 32)
    gemm_mma_xwT<<<gproj, 256>>>(query, Wq, bq, q);
    gemm_mma_xwT<<<gproj, 256>>>(key,   Wk, bk, k);
    gemm_mma_xwT<<<gproj, 256>>>(value, Wv, bv, v);

    dim3 gsc(SS / BN, SS / BM, BB * HH);               // (16, 16, 32)
    scores_kernel<<<gsc, 256>>>(q, k, attn);

    softmax_causal<<<BB * HH * SS, 256>>>(attn);

    dim3 gav(1, SS / BM, BB * HH);                     // (1, 16, 32)
    av_kernel<<<gav, 256>>>(attn, v, x);

    gemm_mma_xwT<<<gproj, 256>>>(x, Wo, bo, out);
}

// round 5
// speedup vs baseline: 1.9208x; 1.2306x over previous
#include <cuda_runtime.h>
#include <cuda_bf16.h>
#include <cstdint>
#include <math.h>

// ---------------------------------------------------------------------------
// Problem constants
// ---------------------------------------------------------------------------
#define BB   2
#define SS   2048
#define DD   2048
#define HH   16
#define DK   128
#define MTOK (BB * SS)          // 4096 tokens
#define SCALE 0.08838834764831845f  // 1/sqrt(128)

// Scratch (device globals; no cudaMalloc allowed)
static __device__ float g_q[(size_t)MTOK * DD];
static __device__ float g_k[(size_t)MTOK * DD];
static __device__ float g_v[(size_t)MTOK * DD];
static __device__ float g_x[(size_t)MTOK * DD];
static __device__ float g_vt[(size_t)BB * HH * DK * SS];        // per-head V^T
static __device__ float g_rpart[(size_t)BB * HH * SS * 16];     // row-sum partials

// ---------------------------------------------------------------------------
// mma.sync helpers (plain sm_80+ PTX: legal on base compute_103 target)
// ---------------------------------------------------------------------------
#define LDSM_X4(r0, r1, r2, r3, addr) \
    asm volatile("ldmatrix.sync.aligned.m8n8.x4.shared.b16 {%0,%1,%2,%3}, [%4];" \
        : "=r"(r0), "=r"(r1), "=r"(r2), "=r"(r3) : "r"(addr))

#define MMA16816(c, a0, a1, a2, a3, b0, b1) \
    asm volatile("mma.sync.aligned.m16n8k16.row.col.f32.bf16.bf16.f32 " \
        "{%0,%1,%2,%3}, {%4,%5,%6,%7}, {%8,%9}, {%0,%1,%2,%3};" \
        : "+f"((c)[0]), "+f"((c)[1]), "+f"((c)[2]), "+f"((c)[3]) \
        : "r"(a0), "r"(a1), "r"(a2), "r"(a3), "r"(b0), "r"(b1))

__device__ __forceinline__ uint32_t smem_u32(const void* p) {
    uint32_t a;
    asm("{ .reg .u64 t; cvta.to.shared.u64 t, %1; cvt.u32.u64 %0, t; }"
        : "=r"(a) : "l"(p));
    return a;
}

__device__ __forceinline__ uint32_t pack_bf2(__nv_bfloat16 a, __nv_bfloat16 b) {
    return (uint32_t)__bfloat16_as_ushort(a) |
           ((uint32_t)__bfloat16_as_ushort(b) << 16);
}

__device__ __forceinline__ void split4(const float4 f, uint2& hi, uint2& lo) {
    __nv_bfloat16 h0 = __float2bfloat16_rn(f.x);
    __nv_bfloat16 h1 = __float2bfloat16_rn(f.y);
    __nv_bfloat16 h2 = __float2bfloat16_rn(f.z);
    __nv_bfloat16 h3 = __float2bfloat16_rn(f.w);
    __nv_bfloat16 l0 = __float2bfloat16_rn(f.x - __bfloat162float(h0));
    __nv_bfloat16 l1 = __float2bfloat16_rn(f.y - __bfloat162float(h1));
    __nv_bfloat16 l2 = __float2bfloat16_rn(f.z - __bfloat162float(h2));
    __nv_bfloat16 l3 = __float2bfloat16_rn(f.w - __bfloat162float(h3));
    hi.x = pack_bf2(h0, h1); hi.y = pack_bf2(h2, h3);
    lo.x = pack_bf2(l0, l1); lo.y = pack_bf2(l2, l3);
}

// ---------------------------------------------------------------------------
// Shared tile-pipeline pieces (128x128 tile, 32-wide K chunks, 256 threads)
// smem: 4 bf16 planes (Ahi, Alo, Bhi, Blo), 128 rows x 32 elems, 80B stride.
// ---------------------------------------------------------------------------
#define RSTRIDE 80                      // bytes per smem row
#define PL_AHI 0
#define PL_ALO 10240
#define PL_BHI 20480
#define PL_BLO 30720

// Core: runs the whole K loop given row-strided A/B global pointers.
// Ag/Bg already offset to (tile row rbase, k-quad kq). Strides in floats.
struct MmaCore {
    float acc[4][4][4];

    __device__ __forceinline__ void run(
        char* sm, const uint32_t sbase,
        const float* Ag, size_t strideA,
        const float* Bg, size_t strideB,
        const int nIter, const int tid)
    {
        const int lane = tid & 31;
        const int wid  = tid >> 5;
        const int wm   = wid >> 2;
        const int wn   = wid & 3;
        const int kq    = tid & 7;
        const int rbase = tid >> 3;

        #pragma unroll
        for (int i = 0; i < 4; i++)
            #pragma unroll
            for (int j = 0; j < 4; j++)
                #pragma unroll
                for (int c = 0; c < 4; c++) acc[i][j][c] = 0.0f;

        const uint32_t aAddr = sbase + PL_AHI
            + (uint32_t)(wm * 64 + (lane & 15)) * RSTRIDE + (lane >> 4) * 16;
        const uint32_t bAddr = sbase + PL_BHI
            + (uint32_t)(wn * 32 + (lane & 7) + ((lane >> 4) & 1) * 8) * RSTRIDE
            + ((lane >> 3) & 1) * 16;

        float4 aS[4], bS[4];
        #pragma unroll
        for (int p = 0; p < 4; p++) {
            aS[p] = *(const float4*)(Ag + (size_t)(p * 32) * strideA);
            bS[p] = *(const float4*)(Bg + (size_t)(p * 32) * strideB);
        }
        #pragma unroll
        for (int p = 0; p < 4; p++) {
            const uint32_t off = (uint32_t)(rbase + p * 32) * RSTRIDE + kq * 8;
            uint2 hi, lo;
            split4(aS[p], hi, lo);
            *(uint2*)(sm + PL_AHI + off) = hi;
            *(uint2*)(sm + PL_ALO + off) = lo;
            split4(bS[p], hi, lo);
            *(uint2*)(sm + PL_BHI + off) = hi;
            *(uint2*)(sm + PL_BLO + off) = lo;
        }
        __syncthreads();

        for (int s = 0; s < nIter; s++) {
            if (s + 1 < nIter) {
                const int k0 = (s + 1) * 32;
                #pragma unroll
                for (int p = 0; p < 4; p++) {
                    aS[p] = *(const float4*)(Ag + (size_t)(p * 32) * strideA + k0);
                    bS[p] = *(const float4*)(Bg + (size_t)(p * 32) * strideB + k0);
                }
            }
            #pragma unroll
            for (int kk = 0; kk < 2; kk++) {
                uint32_t ahi[4][4], alo[4][4];
                uint32_t bhi[2][4], blo[2][4];
                #pragma unroll
                for (int mt = 0; mt < 4; mt++) {
                    const uint32_t a = aAddr + mt * (16 * RSTRIDE) + kk * 32;
                    LDSM_X4(ahi[mt][0], ahi[mt][1], ahi[mt][2], ahi[mt][3], a);
                    LDSM_X4(alo[mt][0], alo[mt][1], alo[mt][2], alo[mt][3],
                            a + (PL_ALO - PL_AHI));
                }
                #pragma unroll
                for (int pp = 0; pp < 2; pp++) {
                    const uint32_t b = bAddr + pp * (16 * RSTRIDE) + kk * 32;
                    LDSM_X4(bhi[pp][0], bhi[pp][1], bhi[pp][2], bhi[pp][3], b);
                    LDSM_X4(blo[pp][0], blo[pp][1], blo[pp][2], blo[pp][3],
                            b + (PL_BLO - PL_BHI));
                }
                #pragma unroll
                for (int mt = 0; mt < 4; mt++) {
                    #pragma unroll
                    for (int pp = 0; pp < 2; pp++) {
                        #pragma unroll
                        for (int t = 0; t < 2; t++) {
                            const int nt = pp * 2 + t;
                            MMA16816(acc[mt][nt],
                                     ahi[mt][0], ahi[mt][1], ahi[mt][2], ahi[mt][3],
                                     bhi[pp][t * 2], bhi[pp][t * 2 + 1]);
                            MMA16816(acc[mt][nt],
                                     ahi[mt][0], ahi[mt][1], ahi[mt][2], ahi[mt][3],
                                     blo[pp][t * 2], blo[pp][t * 2 + 1]);
                            MMA16816(acc[mt][nt],
                                     alo[mt][0], alo[mt][1], alo[mt][2], alo[mt][3],
                                     bhi[pp][t * 2], bhi[pp][t * 2 + 1]);
                        }
                    }
                }
            }
            __syncthreads();
            if (s + 1 < nIter) {
                #pragma unroll
                for (int p = 0; p < 4; p++) {
                    const uint32_t off = (uint32_t)(rbase + p * 32) * RSTRIDE + kq * 8;
                    uint2 hi, lo;
                    split4(aS[p], hi, lo);
                    *(uint2*)(sm + PL_AHI + off) = hi;
                    *(uint2*)(sm + PL_ALO + off) = lo;
                    split4(bS[p], hi, lo);
                    *(uint2*)(sm + PL_BHI + off) = hi;
                    *(uint2*)(sm + PL_BLO + off) = lo;
                }
                __syncthreads();
            }
        }
    }
};

// ---------------------------------------------------------------------------
// Projection GEMM: C = A @ W^T + bias  (A:[M,2048], W:[N,2048])
// ---------------------------------------------------------------------------
__global__ __launch_bounds__(256) void gemm_mma_xwT(
    const float* __restrict__ A, const float* __restrict__ W,
    const float* __restrict__ bias, float* __restrict__ C)
{
    __shared__ __align__(16) char sm[40960];
    const uint32_t sbase = smem_u32(sm);
    const int tid  = threadIdx.x;
    const int lane = tid & 31;
    const int wid  = tid >> 5;
    const int wm   = wid >> 2;
    const int wn   = wid & 3;
    const int bn   = blockIdx.x;
    const int bm   = blockIdx.y;
    const int kq    = tid & 7;
    const int rbase = tid >> 3;

    const float* Ag = A + (size_t)(bm * 128 + rbase) * DD + kq * 4;
    const float* Bg = W + (size_t)(bn * 128 + rbase) * DD + kq * 4;

    MmaCore core;
    core.run(sm, sbase, Ag, DD, Bg, DD, DD / 32, tid);

    #pragma unroll
    for (int mt = 0; mt < 4; mt++) {
        const int row = bm * 128 + wm * 64 + mt * 16 + (lane >> 2);
        #pragma unroll
        for (int nt = 0; nt < 4; nt++) {
            const int col = bn * 128 + wn * 32 + nt * 8 + (lane & 3) * 2;
            const float b0 = bias[col], b1 = bias[col + 1];
            float2 o0, o1;
            o0.x = core.acc[mt][nt][0] + b0; o0.y = core.acc[mt][nt][1] + b1;
            o1.x = core.acc[mt][nt][2] + b0; o1.y = core.acc[mt][nt][3] + b1;
            *(float2*)(C + (size_t)row * DD + col) = o0;
            *(float2*)(C + (size_t)(row + 8) * DD + col) = o1;
        }
    }
}

// ---------------------------------------------------------------------------
// Scores+exp: E[bh,i,j] = exp((q_i.k_j)*SCALE) for j<=i, 0 above diagonal.
// Writes deterministic per-tile row-sum partials to rpart[bh][row][bn].
// Upper-triangle tiles: pure zero-fill.
// ---------------------------------------------------------------------------
__global__ __launch_bounds__(256) void scores_exp_kernel(
    const float* __restrict__ q, const float* __restrict__ k,
    float* __restrict__ attn, float* __restrict__ rpart)
{
    const int bn = blockIdx.x;
    const int bm = blockIdx.y;
    const int bh = blockIdx.z;
    float* out = attn + (size_t)bh * SS * SS;
    const int tid = threadIdx.x;

    if (bn > bm) {  // fully masked tile: zero-fill
        const int row = bm * 128 + (tid >> 1);
        const int c0  = bn * 128 + (tid & 1) * 64;
        const float4 z = make_float4(0.f, 0.f, 0.f, 0.f);
        #pragma unroll
        for (int c = 0; c < 16; c++)
            *(float4*)(out + (size_t)row * SS + c0 + c * 4) = z;
        return;
    }

    __shared__ __align__(16) char sm[40960];
    __shared__ float rs[128][4];
    const uint32_t sbase = smem_u32(sm);
    const int lane = tid & 31;
    const int wid  = tid >> 5;
    const int wm   = wid >> 2;
    const int wn   = wid & 3;
    const int b = bh / HH, h = bh % HH;
    const int kq    = tid & 7;
    const int rbase = tid >> 3;

    const float* Ag = q + (size_t)(b * SS + bm * 128 + rbase) * DD + h * DK + kq * 4;
    const float* Bg = k + (size_t)(b * SS + bn * 128 + rbase) * DD + h * DK + kq * 4;

    MmaCore core;
    core.run(sm, sbase, Ag, DD, Bg, DD, DK / 32, tid);

    // Epilogue: E = exp(acc*SCALE) with causal mask; write + row-sum partials
    float rsum[4][2];
    #pragma unroll
    for (int mt = 0; mt < 4; mt++) { rsum[mt][0] = 0.f; rsum[mt][1] = 0.f; }

    #pragma unroll
    for (int mt = 0; mt < 4; mt++) {
        const int r0 = bm * 128 + wm * 64 + mt * 16 + (lane >> 2);
        const int r1 = r0 + 8;
        #pragma unroll
        for (int nt = 0; nt < 4; nt++) {
            const int col = bn * 128 + wn * 32 + nt * 8 + (lane & 3) * 2;
            float e0 = (col     <= r0) ? __expf(core.acc[mt][nt][0] * SCALE) : 0.f;
            float e1 = (col + 1 <= r0) ? __expf(core.acc[mt][nt][1] * SCALE) : 0.f;
            float e2 = (col     <= r1) ? __expf(core.acc[mt][nt][2] * SCALE) : 0.f;
            float e3 = (col + 1 <= r1) ? __expf(core.acc[mt][nt][3] * SCALE) : 0.f;
            rsum[mt][0] += e0 + e1;
            rsum[mt][1] += e2 + e3;
            float2 o0 = make_float2(e0, e1);
            float2 o1 = make_float2(e2, e3);
            *(float2*)(out + (size_t)r0 * SS + col) = o0;
            *(float2*)(out + (size_t)r1 * SS + col) = o1;
        }
    }

    // Reduce row sums: 4 lanes (lane&3) hold disjoint cols of same row
    #pragma unroll
    for (int mt = 0; mt < 4; mt++) {
        #pragma unroll
        for (int hf = 0; hf < 2; hf++) {
            float v = rsum[mt][hf];
            v += __shfl_xor_sync(0xffffffffu, v, 1);
            v += __shfl_xor_sync(0xffffffffu, v, 2);
            if ((lane & 3) == 0) {
                const int lrow = wm * 64 + mt * 16 + hf * 8 + (lane >> 2);
                rs[lrow][wn] = v;
            }
        }
    }
    __syncthreads();
    if (tid < 128) {
        const float p = rs[tid][0] + rs[tid][1] + rs[tid][2] + rs[tid][3];
        rpart[((size_t)bh * SS + bm * 128 + tid) * 16 + bn] = p;
    }
}

// ---------------------------------------------------------------------------
// Normalize: row /= sum(partials), lower-tri prefix only (tail already 0).
// Deterministic fixed-order partial sum.
// ---------------------------------------------------------------------------
__global__ __launch_bounds__(256) void normalize_kernel(
    float* __restrict__ attn, const float* __restrict__ rpart)
{
    const int blk = blockIdx.x;           // bh*SS + s
    const int s   = blk & (SS - 1);
    __shared__ float sinv;
    if (threadIdx.x == 0) {
        const float* p = rpart + (size_t)blk * 16;
        const int nb = (s >> 7) + 1;
        float sum = 0.f;
        for (int i = 0; i < nb; i++) sum += p[i];
        sinv = 1.0f / sum;
    }
    __syncthreads();
    const float inv = sinv;
    float* row = attn + (size_t)blk * SS;
    const int valid = s + 1;
    for (int j = threadIdx.x * 4; j < valid; j += 1024) {
        float4 v = *(float4*)(row + j);
        v.x *= inv; v.y *= inv; v.z *= inv; v.w *= inv;
        *(float4*)(row + j) = v;
    }
}

// ---------------------------------------------------------------------------
// Transpose V per head: vt[bh][d][s] = v[b][s][h*DK+d]
// ---------------------------------------------------------------------------
__global__ __launch_bounds__(256) void transpose_v(
    const float* __restrict__ v, float* __restrict__ vt)
{
    __shared__ float t[32][33];
    const int bh = blockIdx.z, b = bh / HH, h = bh % HH;
    const int s0 = blockIdx.x * 32, d0 = blockIdx.y * 32;
    const int tx = threadIdx.x & 31, ty = threadIdx.x >> 5;
    #pragma unroll
    for (int i = 0; i < 4; i++)
        t[ty + i * 8][tx] =
            v[(size_t)(b * SS + s0 + ty + i * 8) * DD + h * DK + d0 + tx];
    __syncthreads();
    #pragma unroll
    for (int i = 0; i < 4; i++)
        vt[(size_t)bh * DK * SS + (size_t)(d0 + ty + i * 8) * SS + s0 + tx] =
            t[tx][ty + i * 8];
}

// ---------------------------------------------------------------------------
// AV: x[bh rows, DK] = attn @ V, K truncated at diagonal. B = vt (K-contig).
// ---------------------------------------------------------------------------
__global__ __launch_bounds__(256) void av_mma_kernel(
    const float* __restrict__ attn, const float* __restrict__ vt,
    float* __restrict__ x)
{
    __shared__ __align__(16) char sm[40960];
    const uint32_t sbase = smem_u32(sm);
    const int bm = blockIdx.x;
    const int bh = blockIdx.y;
    const int b = bh / HH, h = bh % HH;
    const int tid  = threadIdx.x;
    const int lane = tid & 31;
    const int wid  = tid >> 5;
    const int wm   = wid >> 2;
    const int wn   = wid & 3;
    const int kq    = tid & 7;
    const int rbase = tid >> 3;

    const float* Ag = attn + (size_t)bh * SS * SS
                    + (size_t)(bm * 128 + rbase) * SS + kq * 4;
    const float* Bg = vt + (size_t)bh * DK * SS + (size_t)rbase * SS + kq * 4;

    MmaCore core;
    core.run(sm, sbase, Ag, SS, Bg, SS, (bm + 1) * 4, tid);

    #pragma unroll
    for (int mt = 0; mt < 4; mt++) {
        const int row = bm * 128 + wm * 64 + mt * 16 + (lane >> 2);
        #pragma unroll
        for (int nt = 0; nt < 4; nt++) {
            const int col = wn * 32 + nt * 8 + (lane & 3) * 2;
            float2 o0, o1;
            o0.x = core.acc[mt][nt][0]; o0.y = core.acc[mt][nt][1];
            o1.x = core.acc[mt][nt][2]; o1.y = core.acc[mt][nt][3];
            *(float2*)(x + (size_t)(b * SS + row) * DD + h * DK + col) = o0;
            *(float2*)(x + (size_t)(b * SS + row + 8) * DD + h * DK + col) = o1;
        }
    }
}

// ---------------------------------------------------------------------------
extern "C" void kernel_launch(void* const* d_in, const int* in_sizes, int n_in,
                              void* d_out, int out_size)
{
    const float* query = (const float*)d_in[0];
    const float* key   = (const float*)d_in[1];
    const float* value = (const float*)d_in[2];
    const float* Wq = (const float*)d_in[3];
    const float* bq = (const float*)d_in[4];
    const float* Wk = (const float*)d_in[5];
    const float* bk = (const float*)d_in[6];
    const float* Wv = (const float*)d_in[7];
    const float* bv = (const float*)d_in[8];
    const float* Wo = (const float*)d_in[9];
    const float* bo = (const float*)d_in[10];

    float* out  = (float*)d_out;                       // [4096, 2048]
    float* attn = out + (size_t)MTOK * DD;             // [32, 2048, 2048]

    float *q, *k, *v, *x, *vt, *rpart;
    cudaGetSymbolAddress((void**)&q, g_q);
    cudaGetSymbolAddress((void**)&k, g_k);
    cudaGetSymbolAddress((void**)&v, g_v);
    cudaGetSymbolAddress((void**)&x, g_x);
    cudaGetSymbolAddress((void**)&vt, g_vt);
    cudaGetSymbolAddress((void**)&rpart, g_rpart);

    dim3 gproj(DD / 128, MTOK / 128);                  // (16, 32)
    gemm_mma_xwT<<<gproj, 256>>>(query, Wq, bq, q);
    gemm_mma_xwT<<<gproj, 256>>>(key,   Wk, bk, k);
    gemm_mma_xwT<<<gproj, 256>>>(value, Wv, bv, v);

    dim3 gtr(SS / 32, DK / 32, BB * HH);               // (64, 4, 32)
    transpose_v<<<gtr, 256>>>(v, vt);

    dim3 gsc(SS / 128, SS / 128, BB * HH);             // (16, 16, 32)
    scores_exp_kernel<<<gsc, 256>>>(q, k, attn, rpart);

    normalize_kernel<<<BB * HH * SS, 256>>>(attn, rpart);

    dim3 gav(SS / 128, BB * HH);                       // (16, 32)
    av_mma_kernel<<<gav, 256>>>(attn, vt, x);

    gemm_mma_xwT<<<gproj, 256>>>(x, Wo, bo, out);
}

// round 6
// speedup vs baseline: 2.0787x; 1.0822x over previous
#include <cuda_runtime.h>
#include <cuda_bf16.h>
#include <cstdint>
#include <math.h>

// ---------------------------------------------------------------------------
// Problem constants
// ---------------------------------------------------------------------------
#define BB   2
#define SS   2048
#define DD   2048
#define HH   16
#define DK   128
#define MTOK (BB * SS)          // 4096 tokens
#define SCALE 0.08838834764831845f  // 1/sqrt(128)

// Scratch (device globals; no cudaMalloc allowed)
static __device__ float g_v [(size_t)MTOK * DD];
static __device__ float g_vt[(size_t)BB * HH * DK * SS];
static __device__ float g_rpart[(size_t)BB * HH * SS * 16];
// bf16 hi/lo planes
static __device__ __nv_bfloat16 g_qih[(size_t)MTOK * DD], g_qil[(size_t)MTOK * DD];
static __device__ __nv_bfloat16 g_kih[(size_t)MTOK * DD], g_kil[(size_t)MTOK * DD];
static __device__ __nv_bfloat16 g_vih[(size_t)MTOK * DD], g_vil[(size_t)MTOK * DD];
static __device__ __nv_bfloat16 g_wh[(size_t)4 * DD * DD], g_wl[(size_t)4 * DD * DD];
static __device__ __nv_bfloat16 g_qh[(size_t)MTOK * DD], g_ql[(size_t)MTOK * DD];
static __device__ __nv_bfloat16 g_kh[(size_t)MTOK * DD], g_kl[(size_t)MTOK * DD];
static __device__ __nv_bfloat16 g_xh[(size_t)MTOK * DD], g_xl[(size_t)MTOK * DD];

// ---------------------------------------------------------------------------
// PTX helpers
// ---------------------------------------------------------------------------
#define LDSM_X4(r0, r1, r2, r3, addr) \
    asm volatile("ldmatrix.sync.aligned.m8n8.x4.shared.b16 {%0,%1,%2,%3}, [%4];" \
        : "=r"(r0), "=r"(r1), "=r"(r2), "=r"(r3) : "r"(addr))

#define MMA16816(c, a0, a1, a2, a3, b0, b1) \
    asm volatile("mma.sync.aligned.m16n8k16.row.col.f32.bf16.bf16.f32 " \
        "{%0,%1,%2,%3}, {%4,%5,%6,%7}, {%8,%9}, {%0,%1,%2,%3};" \
        : "+f"((c)[0]), "+f"((c)[1]), "+f"((c)[2]), "+f"((c)[3]) \
        : "r"(a0), "r"(a1), "r"(a2), "r"(a3), "r"(b0), "r"(b1))

#define CP16(dst, src) \
    asm volatile("cp.async.cg.shared.global [%0], [%1], 16;" \
        :: "r"(dst), "l"(src))
#define CPCOMMIT() asm volatile("cp.async.commit_group;" ::: "memory")
#define CPWAIT1()  asm volatile("cp.async.wait_group 1;" ::: "memory")
#define CPWAIT0()  asm volatile("cp.async.wait_group 0;" ::: "memory")

__device__ __forceinline__ uint32_t smem_u32(const void* p) {
    uint32_t a;
    asm("{ .reg .u64 t; cvta.to.shared.u64 t, %1; cvt.u32.u64 %0, t; }"
        : "=r"(a) : "l"(p));
    return a;
}

__device__ __forceinline__ uint32_t pack_bf2(__nv_bfloat16 a, __nv_bfloat16 b) {
    return (uint32_t)__bfloat16_as_ushort(a) |
           ((uint32_t)__bfloat16_as_ushort(b) << 16);
}

__device__ __forceinline__ void split4(const float4 f, uint2& hi, uint2& lo) {
    __nv_bfloat16 h0 = __float2bfloat16_rn(f.x);
    __nv_bfloat16 h1 = __float2bfloat16_rn(f.y);
    __nv_bfloat16 h2 = __float2bfloat16_rn(f.z);
    __nv_bfloat16 h3 = __float2bfloat16_rn(f.w);
    __nv_bfloat16 l0 = __float2bfloat16_rn(f.x - __bfloat162float(h0));
    __nv_bfloat16 l1 = __float2bfloat16_rn(f.y - __bfloat162float(h1));
    __nv_bfloat16 l2 = __float2bfloat16_rn(f.z - __bfloat162float(h2));
    __nv_bfloat16 l3 = __float2bfloat16_rn(f.w - __bfloat162float(h3));
    hi.x = pack_bf2(h0, h1); hi.y = pack_bf2(h2, h3);
    lo.x = pack_bf2(l0, l1); lo.y = pack_bf2(l2, l3);
}

// ---------------------------------------------------------------------------
// Tile geometry: 128x128 tile, 32-wide K chunks, 256 threads.
// smem: planes Ahi/Alo/Bhi/Blo, 128 rows x 32 bf16, 80B row stride.
// ---------------------------------------------------------------------------
#define RSTRIDE 80
#define PL_AHI 0
#define PL_ALO 10240
#define PL_BHI 20480
#define PL_BLO 30720
#define STAGE_BYTES 40960

// ---------------------------------------------------------------------------
// MmaB16: operands pre-split bf16 hi/lo planes; cp.async double-buffered.
// ---------------------------------------------------------------------------
struct MmaB16 {
    float acc[4][4][4];

    __device__ __forceinline__ static void issue(
        uint32_t sb,
        const __nv_bfloat16* Ah, const __nv_bfloat16* Al, size_t sA,
        const __nv_bfloat16* Bh, const __nv_bfloat16* Bl, size_t sB,
        int k0, int tid)
    {
        #pragma unroll
        for (int i = 0; i < 2; i++) {
            const int ch = tid * 2 + i;
            const int r = ch >> 2, c = ch & 3;
            const uint32_t so = (uint32_t)r * RSTRIDE + c * 16;
            const size_t oA = (size_t)r * sA + k0 + c * 8;
            const size_t oB = (size_t)r * sB + k0 + c * 8;
            CP16(sb + PL_AHI + so, Ah + oA);
            CP16(sb + PL_ALO + so, Al + oA);
            CP16(sb + PL_BHI + so, Bh + oB);
            CP16(sb + PL_BLO + so, Bl + oB);
        }
    }

    __device__ __forceinline__ void run(
        uint32_t sbase,
        const __nv_bfloat16* Ah, const __nv_bfloat16* Al, size_t sA,
        const __nv_bfloat16* Bh, const __nv_bfloat16* Bl, size_t sB,
        const int nIter, const int tid)
    {
        const int lane = tid & 31;
        const int wid  = tid >> 5;
        const int wm   = wid >> 2;
        const int wn   = wid & 3;

        #pragma unroll
        for (int i = 0; i < 4; i++)
            #pragma unroll
            for (int j = 0; j < 4; j++)
                #pragma unroll
                for (int c = 0; c < 4; c++) acc[i][j][c] = 0.0f;

        const uint32_t aAddr = sbase + PL_AHI
            + (uint32_t)(wm * 64 + (lane & 15)) * RSTRIDE + (lane >> 4) * 16;
        const uint32_t bAddr = sbase + PL_BHI
            + (uint32_t)(wn * 32 + (lane & 7) + ((lane >> 4) & 1) * 8) * RSTRIDE
            + ((lane >> 3) & 1) * 16;

        issue(sbase, Ah, Al, sA, Bh, Bl, sB, 0, tid);
        CPCOMMIT();

        for (int s = 0; s < nIter; s++) {
            if (s + 1 < nIter) {
                issue(sbase + ((s + 1) & 1) * STAGE_BYTES,
                      Ah, Al, sA, Bh, Bl, sB, (s + 1) * 32, tid);
                CPCOMMIT();
                CPWAIT1();
            } else {
                CPWAIT0();
            }
            __syncthreads();

            const uint32_t bufo = (uint32_t)(s & 1) * STAGE_BYTES;
            #pragma unroll
            for (int kk = 0; kk < 2; kk++) {
                uint32_t ahi[4][4], alo[4][4];
                uint32_t bhi[2][4], blo[2][4];
                #pragma unroll
                for (int mt = 0; mt < 4; mt++) {
                    const uint32_t a = aAddr + bufo + mt * (16 * RSTRIDE) + kk * 32;
                    LDSM_X4(ahi[mt][0], ahi[mt][1], ahi[mt][2], ahi[mt][3], a);
                    LDSM_X4(alo[mt][0], alo[mt][1], alo[mt][2], alo[mt][3],
                            a + (PL_ALO - PL_AHI));
                }
                #pragma unroll
                for (int pp = 0; pp < 2; pp++) {
                    const uint32_t b = bAddr + bufo + pp * (16 * RSTRIDE) + kk * 32;
                    LDSM_X4(bhi[pp][0], bhi[pp][1], bhi[pp][2], bhi[pp][3], b);
                    LDSM_X4(blo[pp][0], blo[pp][1], blo[pp][2], blo[pp][3],
                            b + (PL_BLO - PL_BHI));
                }
                #pragma unroll
                for (int mt = 0; mt < 4; mt++) {
                    #pragma unroll
                    for (int pp = 0; pp < 2; pp++) {
                        #pragma unroll
                        for (int t = 0; t < 2; t++) {
                            const int nt = pp * 2 + t;
                            MMA16816(acc[mt][nt],
                                     ahi[mt][0], ahi[mt][1], ahi[mt][2], ahi[mt][3],
                                     bhi[pp][t * 2], bhi[pp][t * 2 + 1]);
                            MMA16816(acc[mt][nt],
                                     ahi[mt][0], ahi[mt][1], ahi[mt][2], ahi[mt][3],
                                     blo[pp][t * 2], blo[pp][t * 2 + 1]);
                            MMA16816(acc[mt][nt],
                                     alo[mt][0], alo[mt][1], alo[mt][2], alo[mt][3],
                                     bhi[pp][t * 2], bhi[pp][t * 2 + 1]);
                        }
                    }
                }
            }
            __syncthreads();
        }
    }
};

// ---------------------------------------------------------------------------
// Old fp32-operand core (kept for AV, where A = attn must stay fp32)
// ---------------------------------------------------------------------------
struct MmaCore {
    float acc[4][4][4];

    __device__ __forceinline__ void run(
        char* sm, const uint32_t sbase,
        const float* Ag, size_t strideA,
        const float* Bg, size_t strideB,
        const int nIter, const int tid)
    {
        const int lane = tid & 31;
        const int wid  = tid >> 5;
        const int wm   = wid >> 2;
        const int wn   = wid & 3;
        const int kq    = tid & 7;
        const int rbase = tid >> 3;

        #pragma unroll
        for (int i = 0; i < 4; i++)
            #pragma unroll
            for (int j = 0; j < 4; j++)
                #pragma unroll
                for (int c = 0; c < 4; c++) acc[i][j][c] = 0.0f;

        const uint32_t aAddr = sbase + PL_AHI
            + (uint32_t)(wm * 64 + (lane & 15)) * RSTRIDE + (lane >> 4) * 16;
        const uint32_t bAddr = sbase + PL_BHI
            + (uint32_t)(wn * 32 + (lane & 7) + ((lane >> 4) & 1) * 8) * RSTRIDE
            + ((lane >> 3) & 1) * 16;

        float4 aS[4], bS[4];
        #pragma unroll
        for (int p = 0; p < 4; p++) {
            aS[p] = *(const float4*)(Ag + (size_t)(p * 32) * strideA);
            bS[p] = *(const float4*)(Bg + (size_t)(p * 32) * strideB);
        }
        #pragma unroll
        for (int p = 0; p < 4; p++) {
            const uint32_t off = (uint32_t)(rbase + p * 32) * RSTRIDE + kq * 8;
            uint2 hi, lo;
            split4(aS[p], hi, lo);
            *(uint2*)(sm + PL_AHI + off) = hi;
            *(uint2*)(sm + PL_ALO + off) = lo;
            split4(bS[p], hi, lo);
            *(uint2*)(sm + PL_BHI + off) = hi;
            *(uint2*)(sm + PL_BLO + off) = lo;
        }
        __syncthreads();

        for (int s = 0; s < nIter; s++) {
            if (s + 1 < nIter) {
                const int k0 = (s + 1) * 32;
                #pragma unroll
                for (int p = 0; p < 4; p++) {
                    aS[p] = *(const float4*)(Ag + (size_t)(p * 32) * strideA + k0);
                    bS[p] = *(const float4*)(Bg + (size_t)(p * 32) * strideB + k0);
                }
            }
            #pragma unroll
            for (int kk = 0; kk < 2; kk++) {
                uint32_t ahi[4][4], alo[4][4];
                uint32_t bhi[2][4], blo[2][4];
                #pragma unroll
                for (int mt = 0; mt < 4; mt++) {
                    const uint32_t a = aAddr + mt * (16 * RSTRIDE) + kk * 32;
                    LDSM_X4(ahi[mt][0], ahi[mt][1], ahi[mt][2], ahi[mt][3], a);
                    LDSM_X4(alo[mt][0], alo[mt][1], alo[mt][2], alo[mt][3],
                            a + (PL_ALO - PL_AHI));
                }
                #pragma unroll
                for (int pp = 0; pp < 2; pp++) {
                    const uint32_t b = bAddr + pp * (16 * RSTRIDE) + kk * 32;
                    LDSM_X4(bhi[pp][0], bhi[pp][1], bhi[pp][2], bhi[pp][3], b);
                    LDSM_X4(blo[pp][0], blo[pp][1], blo[pp][2], blo[pp][3],
                            b + (PL_BLO - PL_BHI));
                }
                #pragma unroll
                for (int mt = 0; mt < 4; mt++) {
                    #pragma unroll
                    for (int pp = 0; pp < 2; pp++) {
                        #pragma unroll
                        for (int t = 0; t < 2; t++) {
                            const int nt = pp * 2 + t;
                            MMA16816(acc[mt][nt],
                                     ahi[mt][0], ahi[mt][1], ahi[mt][2], ahi[mt][3],
                                     bhi[pp][t * 2], bhi[pp][t * 2 + 1]);
                            MMA16816(acc[mt][nt],
                                     ahi[mt][0], ahi[mt][1], ahi[mt][2], ahi[mt][3],
                                     blo[pp][t * 2], blo[pp][t * 2 + 1]);
                            MMA16816(acc[mt][nt],
                                     alo[mt][0], alo[mt][1], alo[mt][2], alo[mt][3],
                                     bhi[pp][t * 2], bhi[pp][t * 2 + 1]);
                        }
                    }
                }
            }
            __syncthreads();
            if (s + 1 < nIter) {
                #pragma unroll
                for (int p = 0; p < 4; p++) {
                    const uint32_t off = (uint32_t)(rbase + p * 32) * RSTRIDE + kq * 8;
                    uint2 hi, lo;
                    split4(aS[p], hi, lo);
                    *(uint2*)(sm + PL_AHI + off) = hi;
                    *(uint2*)(sm + PL_ALO + off) = lo;
                    split4(bS[p], hi, lo);
                    *(uint2*)(sm + PL_BHI + off) = hi;
                    *(uint2*)(sm + PL_BLO + off) = lo;
                }
                __syncthreads();
            }
        }
    }
};

// ---------------------------------------------------------------------------
// Split fp32 tensors into bf16 hi/lo planes (batched over blockIdx.y)
// ---------------------------------------------------------------------------
__global__ __launch_bounds__(256) void split_inputs(
    const float* __restrict__ a0, const float* __restrict__ a1,
    const float* __restrict__ a2,
    __nv_bfloat16* __restrict__ h0, __nv_bfloat16* __restrict__ l0,
    __nv_bfloat16* __restrict__ h1, __nv_bfloat16* __restrict__ l1,
    __nv_bfloat16* __restrict__ h2, __nv_bfloat16* __restrict__ l2)
{
    const int z = blockIdx.y;
    const float* s = (z == 0) ? a0 : (z == 1) ? a1 : a2;
    __nv_bfloat16* H = (z == 0) ? h0 : (z == 1) ? h1 : h2;
    __nv_bfloat16* L = (z == 0) ? l0 : (z == 1) ? l1 : l2;
    const size_t i = ((size_t)blockIdx.x * 256 + threadIdx.x) * 4;
    float4 f = *(const float4*)(s + i);
    uint2 hi, lo;
    split4(f, hi, lo);
    *(uint2*)(H + i) = hi;
    *(uint2*)(L + i) = lo;
}

__global__ __launch_bounds__(256) void split_weights(
    const float* __restrict__ w0, const float* __restrict__ w1,
    const float* __restrict__ w2, const float* __restrict__ w3,
    __nv_bfloat16* __restrict__ wh, __nv_bfloat16* __restrict__ wl)
{
    const int z = blockIdx.y;
    const float* s = (z == 0) ? w0 : (z == 1) ? w1 : (z == 2) ? w2 : w3;
    const size_t base = (size_t)z * DD * DD;
    const size_t i = ((size_t)blockIdx.x * 256 + threadIdx.x) * 4;
    float4 f = *(const float4*)(s + i);
    uint2 hi, lo;
    split4(f, hi, lo);
    *(uint2*)(wh + base + i) = hi;
    *(uint2*)(wl + base + i) = lo;
}

// ---------------------------------------------------------------------------
// Batched Q/K/V projection: z=0 -> q planes, z=1 -> k planes, z=2 -> v fp32
// ---------------------------------------------------------------------------
__global__ __launch_bounds__(256) void proj_qkv(
    const __nv_bfloat16* __restrict__ qih, const __nv_bfloat16* __restrict__ qil,
    const __nv_bfloat16* __restrict__ kih, const __nv_bfloat16* __restrict__ kil,
    const __nv_bfloat16* __restrict__ vih, const __nv_bfloat16* __restrict__ vil,
    const __nv_bfloat16* __restrict__ wh, const __nv_bfloat16* __restrict__ wl,
    const float* __restrict__ bq, const float* __restrict__ bk,
    const float* __restrict__ bv,
    __nv_bfloat16* __restrict__ qh, __nv_bfloat16* __restrict__ ql,
    __nv_bfloat16* __restrict__ kh, __nv_bfloat16* __restrict__ kl,
    float* __restrict__ v)
{
    extern __shared__ char dsm[];
    const uint32_t sbase = smem_u32(dsm);
    const int tid  = threadIdx.x;
    const int lane = tid & 31;
    const int wid  = tid >> 5;
    const int wm   = wid >> 2;
    const int wn   = wid & 3;
    const int bn   = blockIdx.x;
    const int bm   = blockIdx.y;
    const int z    = blockIdx.z;

    const __nv_bfloat16* Ah = (z == 0) ? qih : (z == 1) ? kih : vih;
    const __nv_bfloat16* Al = (z == 0) ? qil : (z == 1) ? kil : vil;
    const float* bias = (z == 0) ? bq : (z == 1) ? bk : bv;
    const size_t wbase = (size_t)z * DD * DD;

    MmaB16 core;
    core.run(sbase,
             Ah + (size_t)(bm * 128) * DD, Al + (size_t)(bm * 128) * DD, DD,
             wh + wbase + (size_t)(bn * 128) * DD,
             wl + wbase + (size_t)(bn * 128) * DD, DD,
             DD / 32, tid);

    #pragma unroll
    for (int mt = 0; mt < 4; mt++) {
        const int row = bm * 128 + wm * 64 + mt * 16 + (lane >> 2);
        #pragma unroll
        for (int nt = 0; nt < 4; nt++) {
            const int col = bn * 128 + wn * 32 + nt * 8 + (lane & 3) * 2;
            const float b0 = bias[col], b1 = bias[col + 1];
            const float v0 = core.acc[mt][nt][0] + b0;
            const float v1 = core.acc[mt][nt][1] + b1;
            const float v2 = core.acc[mt][nt][2] + b0;
            const float v3 = core.acc[mt][nt][3] + b1;
            if (z == 2) {
                *(float2*)(v + (size_t)row * DD + col) = make_float2(v0, v1);
                *(float2*)(v + (size_t)(row + 8) * DD + col) = make_float2(v2, v3);
            } else {
                __nv_bfloat16* H = (z == 0) ? qh : kh;
                __nv_bfloat16* L = (z == 0) ? ql : kl;
                __nv_bfloat16 h0 = __float2bfloat16_rn(v0);
                __nv_bfloat16 h1 = __float2bfloat16_rn(v1);
                __nv_bfloat16 h2 = __float2bfloat16_rn(v2);
                __nv_bfloat16 h3 = __float2bfloat16_rn(v3);
                *(uint32_t*)(H + (size_t)row * DD + col) = pack_bf2(h0, h1);
                *(uint32_t*)(L + (size_t)row * DD + col) = pack_bf2(
                    __float2bfloat16_rn(v0 - __bfloat162float(h0)),
                    __float2bfloat16_rn(v1 - __bfloat162float(h1)));
                *(uint32_t*)(H + (size_t)(row + 8) * DD + col) = pack_bf2(h2, h3);
                *(uint32_t*)(L + (size_t)(row + 8) * DD + col) = pack_bf2(
                    __float2bfloat16_rn(v2 - __bfloat162float(h2)),
                    __float2bfloat16_rn(v3 - __bfloat162float(h3)));
            }
        }
    }
}

// ---------------------------------------------------------------------------
// Final GEMM: out = x @ Wo^T + bo (x, Wo as planes; fp32 out)
// ---------------------------------------------------------------------------
__global__ __launch_bounds__(256) void gemm_b16(
    const __nv_bfloat16* __restrict__ Ah, const __nv_bfloat16* __restrict__ Al,
    const __nv_bfloat16* __restrict__ Wh, const __nv_bfloat16* __restrict__ Wl,
    const float* __restrict__ bias, float* __restrict__ C)
{
    extern __shared__ char dsm[];
    const uint32_t sbase = smem_u32(dsm);
    const int tid  = threadIdx.x;
    const int lane = tid & 31;
    const int wid  = tid >> 5;
    const int wm   = wid >> 2;
    const int wn   = wid & 3;
    const int bn   = blockIdx.x;
    const int bm   = blockIdx.y;

    MmaB16 core;
    core.run(sbase,
             Ah + (size_t)(bm * 128) * DD, Al + (size_t)(bm * 128) * DD, DD,
             Wh + (size_t)(bn * 128) * DD, Wl + (size_t)(bn * 128) * DD, DD,
             DD / 32, tid);

    #pragma unroll
    for (int mt = 0; mt < 4; mt++) {
        const int row = bm * 128 + wm * 64 + mt * 16 + (lane >> 2);
        #pragma unroll
        for (int nt = 0; nt < 4; nt++) {
            const int col = bn * 128 + wn * 32 + nt * 8 + (lane & 3) * 2;
            const float b0 = bias[col], b1 = bias[col + 1];
            float2 o0, o1;
            o0.x = core.acc[mt][nt][0] + b0; o0.y = core.acc[mt][nt][1] + b1;
            o1.x = core.acc[mt][nt][2] + b0; o1.y = core.acc[mt][nt][3] + b1;
            *(float2*)(C + (size_t)row * DD + col) = o0;
            *(float2*)(C + (size_t)(row + 8) * DD + col) = o1;
        }
    }
}

// ---------------------------------------------------------------------------
// Scores+exp from q/k planes; causal; row-sum partials.
// ---------------------------------------------------------------------------
__global__ __launch_bounds__(256) void scores_exp_kernel(
    const __nv_bfloat16* __restrict__ qh, const __nv_bfloat16* __restrict__ ql,
    const __nv_bfloat16* __restrict__ kh, const __nv_bfloat16* __restrict__ kl,
    float* __restrict__ attn, float* __restrict__ rpart)
{
    const int bn = blockIdx.x;
    const int bm = blockIdx.y;
    const int bh = blockIdx.z;
    float* out = attn + (size_t)bh * SS * SS;
    const int tid = threadIdx.x;

    if (bn > bm) {  // fully masked tile: zero-fill
        const int row = bm * 128 + (tid >> 1);
        const int c0  = bn * 128 + (tid & 1) * 64;
        const float4 z = make_float4(0.f, 0.f, 0.f, 0.f);
        #pragma unroll
        for (int c = 0; c < 16; c++)
            *(float4*)(out + (size_t)row * SS + c0 + c * 4) = z;
        return;
    }

    extern __shared__ char dsm[];
    __shared__ float rs[128][4];
    const uint32_t sbase = smem_u32(dsm);
    const int lane = tid & 31;
    const int wid  = tid >> 5;
    const int wm   = wid >> 2;
    const int wn   = wid & 3;
    const int b = bh / HH, h = bh % HH;

    const size_t aoff = (size_t)(b * SS + bm * 128) * DD + h * DK;
    const size_t boff = (size_t)(b * SS + bn * 128) * DD + h * DK;

    MmaB16 core;
    core.run(sbase, qh + aoff, ql + aoff, DD, kh + boff, kl + boff, DD,
             DK / 32, tid);

    float rsum[4][2];
    #pragma unroll
    for (int mt = 0; mt < 4; mt++) { rsum[mt][0] = 0.f; rsum[mt][1] = 0.f; }

    #pragma unroll
    for (int mt = 0; mt < 4; mt++) {
        const int r0 = bm * 128 + wm * 64 + mt * 16 + (lane >> 2);
        const int r1 = r0 + 8;
        #pragma unroll
        for (int nt = 0; nt < 4; nt++) {
            const int col = bn * 128 + wn * 32 + nt * 8 + (lane & 3) * 2;
            float e0 = (col     <= r0) ? __expf(core.acc[mt][nt][0] * SCALE) : 0.f;
            float e1 = (col + 1 <= r0) ? __expf(core.acc[mt][nt][1] * SCALE) : 0.f;
            float e2 = (col     <= r1) ? __expf(core.acc[mt][nt][2] * SCALE) : 0.f;
            float e3 = (col + 1 <= r1) ? __expf(core.acc[mt][nt][3] * SCALE) : 0.f;
            rsum[mt][0] += e0 + e1;
            rsum[mt][1] += e2 + e3;
            *(float2*)(out + (size_t)r0 * SS + col) = make_float2(e0, e1);
            *(float2*)(out + (size_t)r1 * SS + col) = make_float2(e2, e3);
        }
    }

    #pragma unroll
    for (int mt = 0; mt < 4; mt++) {
        #pragma unroll
        for (int hf = 0; hf < 2; hf++) {
            float vv = rsum[mt][hf];
            vv += __shfl_xor_sync(0xffffffffu, vv, 1);
            vv += __shfl_xor_sync(0xffffffffu, vv, 2);
            if ((lane & 3) == 0) {
                const int lrow = wm * 64 + mt * 16 + hf * 8 + (lane >> 2);
                rs[lrow][wn] = vv;
            }
        }
    }
    __syncthreads();
    if (tid < 128) {
        const float p = rs[tid][0] + rs[tid][1] + rs[tid][2] + rs[tid][3];
        rpart[((size_t)bh * SS + bm * 128 + tid) * 16 + bn] = p;
    }
}

// ---------------------------------------------------------------------------
// Normalize rows by partial sums (deterministic fixed order)
// ---------------------------------------------------------------------------
__global__ __launch_bounds__(256) void normalize_kernel(
    float* __restrict__ attn, const float* __restrict__ rpart)
{
    const int blk = blockIdx.x;           // bh*SS + s
    const int s   = blk & (SS - 1);
    __shared__ float sinv;
    if (threadIdx.x == 0) {
        const float* p = rpart + (size_t)blk * 16;
        const int nb = (s >> 7) + 1;
        float sum = 0.f;
        for (int i = 0; i < nb; i++) sum += p[i];
        sinv = 1.0f / sum;
    }
    __syncthreads();
    const float inv = sinv;
    float* row = attn + (size_t)blk * SS;
    const int valid = s + 1;
    for (int j = threadIdx.x * 4; j < valid; j += 1024) {
        float4 v = *(float4*)(row + j);
        v.x *= inv; v.y *= inv; v.z *= inv; v.w *= inv;
        *(float4*)(row + j) = v;
    }
}

// ---------------------------------------------------------------------------
// Transpose V per head: vt[bh][d][s] = v[b][s][h*DK+d]
// ---------------------------------------------------------------------------
__global__ __launch_bounds__(256) void transpose_v(
    const float* __restrict__ v, float* __restrict__ vt)
{
    __shared__ float t[32][33];
    const int bh = blockIdx.z, b = bh / HH, h = bh % HH;
    const int s0 = blockIdx.x * 32, d0 = blockIdx.y * 32;
    const int tx = threadIdx.x & 31, ty = threadIdx.x >> 5;
    #pragma unroll
    for (int i = 0; i < 4; i++)
        t[ty + i * 8][tx] =
            v[(size_t)(b * SS + s0 + ty + i * 8) * DD + h * DK + d0 + tx];
    __syncthreads();
    #pragma unroll
    for (int i = 0; i < 4; i++)
        vt[(size_t)bh * DK * SS + (size_t)(d0 + ty + i * 8) * SS + s0 + tx] =
            t[tx][ty + i * 8];
}

// ---------------------------------------------------------------------------
// AV: x = attn @ V (fp32 core); epilogue writes x planes for final GEMM.
// ---------------------------------------------------------------------------
__global__ __launch_bounds__(256) void av_mma_kernel(
    const float* __restrict__ attn, const float* __restrict__ vt,
    __nv_bfloat16* __restrict__ xh, __nv_bfloat16* __restrict__ xl)
{
    __shared__ __align__(16) char sm[40960];
    const uint32_t sbase = smem_u32(sm);
    const int bm = blockIdx.x;
    const int bh = blockIdx.y;
    const int b = bh / HH, h = bh % HH;
    const int tid  = threadIdx.x;
    const int lane = tid & 31;
    const int wid  = tid >> 5;
    const int wm   = wid >> 2;
    const int wn   = wid & 3;
    const int kq    = tid & 7;
    const int rbase = tid >> 3;

    const float* Ag = attn + (size_t)bh * SS * SS
                    + (size_t)(bm * 128 + rbase) * SS + kq * 4;
    const float* Bg = vt + (size_t)bh * DK * SS + (size_t)rbase * SS + kq * 4;

    MmaCore core;
    core.run(sm, sbase, Ag, SS, Bg, SS, (bm + 1) * 4, tid);

    #pragma unroll
    for (int mt = 0; mt < 4; mt++) {
        const int row = bm * 128 + wm * 64 + mt * 16 + (lane >> 2);
        #pragma unroll
        for (int nt = 0; nt < 4; nt++) {
            const int col = wn * 32 + nt * 8 + (lane & 3) * 2;
            const float v0 = core.acc[mt][nt][0];
            const float v1 = core.acc[mt][nt][1];
            const float v2 = core.acc[mt][nt][2];
            const float v3 = core.acc[mt][nt][3];
            __nv_bfloat16 h0 = __float2bfloat16_rn(v0);
            __nv_bfloat16 h1 = __float2bfloat16_rn(v1);
            __nv_bfloat16 h2 = __float2bfloat16_rn(v2);
            __nv_bfloat16 h3 = __float2bfloat16_rn(v3);
            const size_t o0 = (size_t)(b * SS + row) * DD + h * DK + col;
            const size_t o1 = (size_t)(b * SS + row + 8) * DD + h * DK + col;
            *(uint32_t*)(xh + o0) = pack_bf2(h0, h1);
            *(uint32_t*)(xl + o0) = pack_bf2(
                __float2bfloat16_rn(v0 - __bfloat162float(h0)),
                __float2bfloat16_rn(v1 - __bfloat162float(h1)));
            *(uint32_t*)(xh + o1) = pack_bf2(h2, h3);
            *(uint32_t*)(xl + o1) = pack_bf2(
                __float2bfloat16_rn(v2 - __bfloat162float(h2)),
                __float2bfloat16_rn(v3 - __bfloat162float(h3)));
        }
    }
}

// ---------------------------------------------------------------------------
extern "C" void kernel_launch(void* const* d_in, const int* in_sizes, int n_in,
                              void* d_out, int out_size)
{
    const float* query = (const float*)d_in[0];
    const float* key   = (const float*)d_in[1];
    const float* value = (const float*)d_in[2];
    const float* Wq = (const float*)d_in[3];
    const float* bq = (const float*)d_in[4];
    const float* Wk = (const float*)d_in[5];
    const float* bk = (const float*)d_in[6];
    const float* Wv = (const float*)d_in[7];
    const float* bv = (const float*)d_in[8];
    const float* Wo = (const float*)d_in[9];
    const float* bo = (const float*)d_in[10];

    float* out  = (float*)d_out;                       // [4096, 2048]
    float* attn = out + (size_t)MTOK * DD;             // [32, 2048, 2048]

    float *v, *vt, *rpart;
    __nv_bfloat16 *qih, *qil, *kih, *kil, *vih, *vil, *wh, *wl;
    __nv_bfloat16 *qh, *ql, *kh, *kl, *xh, *xl;
    cudaGetSymbolAddress((void**)&v, g_v);
    cudaGetSymbolAddress((void**)&vt, g_vt);
    cudaGetSymbolAddress((void**)&rpart, g_rpart);
    cudaGetSymbolAddress((void**)&qih, g_qih);
    cudaGetSymbolAddress((void**)&qil, g_qil);
    cudaGetSymbolAddress((void**)&kih, g_kih);
    cudaGetSymbolAddress((void**)&kil, g_kil);
    cudaGetSymbolAddress((void**)&vih, g_vih);
    cudaGetSymbolAddress((void**)&vil, g_vil);
    cudaGetSymbolAddress((void**)&wh, g_wh);
    cudaGetSymbolAddress((void**)&wl, g_wl);
    cudaGetSymbolAddress((void**)&qh, g_qh);
    cudaGetSymbolAddress((void**)&ql, g_ql);
    cudaGetSymbolAddress((void**)&kh, g_kh);
    cudaGetSymbolAddress((void**)&kl, g_kl);
    cudaGetSymbolAddress((void**)&xh, g_xh);
    cudaGetSymbolAddress((void**)&xl, g_xl);

    static bool attrs_set = false;
    if (!attrs_set) {
        cudaFuncSetAttribute(proj_qkv,
            cudaFuncAttributeMaxDynamicSharedMemorySize, 2 * STAGE_BYTES);
        cudaFuncSetAttribute(gemm_b16,
            cudaFuncAttributeMaxDynamicSharedMemorySize, 2 * STAGE_BYTES);
        cudaFuncSetAttribute(scores_exp_kernel,
            cudaFuncAttributeMaxDynamicSharedMemorySize, 2 * STAGE_BYTES);
        attrs_set = true;
    }

    // 1. Split inputs and weights into bf16 planes
    dim3 gsi((MTOK * DD) / (256 * 4), 3);
    split_inputs<<<gsi, 256>>>(query, key, value,
                               qih, qil, kih, kil, vih, vil);
    dim3 gsw((DD * DD) / (256 * 4), 4);
    split_weights<<<gsw, 256>>>(Wq, Wk, Wv, Wo, wh, wl);

    // 2. Batched Q/K/V projections
    dim3 gproj(DD / 128, MTOK / 128, 3);
    proj_qkv<<<gproj, 256, 2 * STAGE_BYTES>>>(
        qih, qil, kih, kil, vih, vil, wh, wl, bq, bk, bv,
        qh, ql, kh, kl, v);

    // 3. V transpose
    dim3 gtr(SS / 32, DK / 32, BB * HH);
    transpose_v<<<gtr, 256>>>(v, vt);

    // 4. Scores + exp (+ partial row sums)
    dim3 gsc(SS / 128, SS / 128, BB * HH);
    scores_exp_kernel<<<gsc, 256, 2 * STAGE_BYTES>>>(qh, ql, kh, kl, attn, rpart);

    // 5. Normalize
    normalize_kernel<<<BB * HH * SS, 256>>>(attn, rpart);

    // 6. AV
    dim3 gav(SS / 128, BB * HH);
    av_mma_kernel<<<gav, 256>>>(attn, vt, xh, xl);

    // 7. Output projection
    dim3 gout(DD / 128, MTOK / 128);
    gemm_b16<<<gout, 256, 2 * STAGE_BYTES>>>(
        xh, xl, wh + (size_t)3 * DD * DD, wl + (size_t)3 * DD * DD, bo, out);
}

// round 7
// speedup vs baseline: 2.4286x; 1.1683x over previous
#include <cuda_runtime.h>
#include <cuda_bf16.h>
#include <cstdint>
#include <math.h>

// ---------------------------------------------------------------------------
// Problem constants
// ---------------------------------------------------------------------------
#define BB   2
#define SS   2048
#define DD   2048
#define HH   16
#define DK   128
#define MTOK (BB * SS)          // 4096 tokens
#define SCALE 0.08838834764831845f  // 1/sqrt(128)

// Scratch (device globals; no cudaMalloc allowed)
static __device__ float g_v [(size_t)MTOK * DD];
static __device__ float g_rpart[(size_t)BB * HH * SS * 16];
// bf16 hi/lo planes
static __device__ __nv_bfloat16 g_qih[(size_t)MTOK * DD], g_qil[(size_t)MTOK * DD];
static __device__ __nv_bfloat16 g_kih[(size_t)MTOK * DD], g_kil[(size_t)MTOK * DD];
static __device__ __nv_bfloat16 g_vih[(size_t)MTOK * DD], g_vil[(size_t)MTOK * DD];
static __device__ __nv_bfloat16 g_wh[(size_t)4 * DD * DD], g_wl[(size_t)4 * DD * DD];
static __device__ __nv_bfloat16 g_qh[(size_t)MTOK * DD], g_ql[(size_t)MTOK * DD];
static __device__ __nv_bfloat16 g_kh[(size_t)MTOK * DD], g_kl[(size_t)MTOK * DD];
static __device__ __nv_bfloat16 g_xh[(size_t)MTOK * DD], g_xl[(size_t)MTOK * DD];
static __device__ __nv_bfloat16 g_vth[(size_t)BB * HH * DK * SS];
static __device__ __nv_bfloat16 g_vtl[(size_t)BB * HH * DK * SS];
// Normalized-P planes (big: 2 x 268MB)
static __device__ __nv_bfloat16 g_ph[(size_t)BB * HH * SS * SS];
static __device__ __nv_bfloat16 g_pl[(size_t)BB * HH * SS * SS];

// ---------------------------------------------------------------------------
// PTX helpers
// ---------------------------------------------------------------------------
#define LDSM_X4(r0, r1, r2, r3, addr) \
    asm volatile("ldmatrix.sync.aligned.m8n8.x4.shared.b16 {%0,%1,%2,%3}, [%4];" \
        : "=r"(r0), "=r"(r1), "=r"(r2), "=r"(r3) : "r"(addr))

#define MMA16816(c, a0, a1, a2, a3, b0, b1) \
    asm volatile("mma.sync.aligned.m16n8k16.row.col.f32.bf16.bf16.f32 " \
        "{%0,%1,%2,%3}, {%4,%5,%6,%7}, {%8,%9}, {%0,%1,%2,%3};" \
        : "+f"((c)[0]), "+f"((c)[1]), "+f"((c)[2]), "+f"((c)[3]) \
        : "r"(a0), "r"(a1), "r"(a2), "r"(a3), "r"(b0), "r"(b1))

#define CP16(dst, src) \
    asm volatile("cp.async.cg.shared.global [%0], [%1], 16;" \
        :: "r"(dst), "l"(src))
#define CPCOMMIT() asm volatile("cp.async.commit_group;" ::: "memory")
#define CPWAIT2()  asm volatile("cp.async.wait_group 2;" ::: "memory")

__device__ __forceinline__ uint32_t smem_u32(const void* p) {
    uint32_t a;
    asm("{ .reg .u64 t; cvta.to.shared.u64 t, %1; cvt.u32.u64 %0, t; }"
        : "=r"(a) : "l"(p));
    return a;
}

__device__ __forceinline__ uint32_t pack_bf2(__nv_bfloat16 a, __nv_bfloat16 b) {
    return (uint32_t)__bfloat16_as_ushort(a) |
           ((uint32_t)__bfloat16_as_ushort(b) << 16);
}

__device__ __forceinline__ void split4(const float4 f, uint2& hi, uint2& lo) {
    __nv_bfloat16 h0 = __float2bfloat16_rn(f.x);
    __nv_bfloat16 h1 = __float2bfloat16_rn(f.y);
    __nv_bfloat16 h2 = __float2bfloat16_rn(f.z);
    __nv_bfloat16 h3 = __float2bfloat16_rn(f.w);
    __nv_bfloat16 l0 = __float2bfloat16_rn(f.x - __bfloat162float(h0));
    __nv_bfloat16 l1 = __float2bfloat16_rn(f.y - __bfloat162float(h1));
    __nv_bfloat16 l2 = __float2bfloat16_rn(f.z - __bfloat162float(h2));
    __nv_bfloat16 l3 = __float2bfloat16_rn(f.w - __bfloat162float(h3));
    hi.x = pack_bf2(h0, h1); hi.y = pack_bf2(h2, h3);
    lo.x = pack_bf2(l0, l1); lo.y = pack_bf2(l2, l3);
}

// ---------------------------------------------------------------------------
// MmaB16v2: 128x128 tile, K-chunk 16, 4-stage cp.async pipeline,
// ONE __syncthreads per stage. smem rows = 16 bf16 + pad (48B stride).
// ---------------------------------------------------------------------------
#define NS 4
#define RS2 48
#define ST_AHI 0
#define ST_ALO 6144
#define ST_BHI 12288
#define ST_BLO 18432
#define ST_BYTES 24576
#define DSMEM_TOTAL (NS * ST_BYTES)   // 98304

struct MmaB16v2 {
    float acc[4][4][4];

    __device__ __forceinline__ static void issue(
        uint32_t sb,
        const __nv_bfloat16* Ah, const __nv_bfloat16* Al, size_t sA,
        const __nv_bfloat16* Bh, const __nv_bfloat16* Bl, size_t sB,
        int k0, int tid)
    {
        const int row  = tid >> 1;
        const int half = tid & 1;
        const uint32_t so = (uint32_t)row * RS2 + half * 16;
        const size_t oA = (size_t)row * sA + k0 + half * 8;
        const size_t oB = (size_t)row * sB + k0 + half * 8;
        CP16(sb + ST_AHI + so, Ah + oA);
        CP16(sb + ST_ALO + so, Al + oA);
        CP16(sb + ST_BHI + so, Bh + oB);
        CP16(sb + ST_BLO + so, Bl + oB);
    }

    __device__ __forceinline__ void run(
        uint32_t sbase,
        const __nv_bfloat16* Ah, const __nv_bfloat16* Al, size_t sA,
        const __nv_bfloat16* Bh, const __nv_bfloat16* Bl, size_t sB,
        const int nIter, const int tid)
    {
        const int lane = tid & 31;
        const int wid  = tid >> 5;
        const int wm   = wid >> 2;
        const int wn   = wid & 3;

        #pragma unroll
        for (int i = 0; i < 4; i++)
            #pragma unroll
            for (int j = 0; j < 4; j++)
                #pragma unroll
                for (int c = 0; c < 4; c++) acc[i][j][c] = 0.0f;

        const uint32_t aAddr = sbase + ST_AHI
            + (uint32_t)(wm * 64 + (lane & 15)) * RS2 + (lane >> 4) * 16;
        const uint32_t bAddr = sbase + ST_BHI
            + (uint32_t)(wn * 32 + (lane & 7) + ((lane >> 4) & 1) * 8) * RS2
            + ((lane >> 3) & 1) * 16;

        #pragma unroll
        for (int p = 0; p < NS - 1; p++) {
            if (p < nIter)
                issue(sbase + p * ST_BYTES, Ah, Al, sA, Bh, Bl, sB, p * 16, tid);
            CPCOMMIT();
        }

        for (int s = 0; s < nIter; s++) {
            CPWAIT2();
            __syncthreads();

            const uint32_t bo = (uint32_t)(s & (NS - 1)) * ST_BYTES;
            uint32_t ahi[4][4], alo[4][4];
            uint32_t bhi[2][4], blo[2][4];
            #pragma unroll
            for (int mt = 0; mt < 4; mt++) {
                const uint32_t a = aAddr + bo + mt * (16 * RS2);
                LDSM_X4(ahi[mt][0], ahi[mt][1], ahi[mt][2], ahi[mt][3], a);
                LDSM_X4(alo[mt][0], alo[mt][1], alo[mt][2], alo[mt][3],
                        a + (ST_ALO - ST_AHI));
            }
            #pragma unroll
            for (int pp = 0; pp < 2; pp++) {
                const uint32_t b = bAddr + bo + pp * (16 * RS2);
                LDSM_X4(bhi[pp][0], bhi[pp][1], bhi[pp][2], bhi[pp][3], b);
                LDSM_X4(blo[pp][0], blo[pp][1], blo[pp][2], blo[pp][3],
                        b + (ST_BLO - ST_BHI));
            }
            #pragma unroll
            for (int mt = 0; mt < 4; mt++) {
                #pragma unroll
                for (int pp = 0; pp < 2; pp++) {
                    #pragma unroll
                    for (int t = 0; t < 2; t++) {
                        const int nt = pp * 2 + t;
                        MMA16816(acc[mt][nt],
                                 ahi[mt][0], ahi[mt][1], ahi[mt][2], ahi[mt][3],
                                 bhi[pp][t * 2], bhi[pp][t * 2 + 1]);
                        MMA16816(acc[mt][nt],
                                 ahi[mt][0], ahi[mt][1], ahi[mt][2], ahi[mt][3],
                                 blo[pp][t * 2], blo[pp][t * 2 + 1]);
                        MMA16816(acc[mt][nt],
                                 alo[mt][0], alo[mt][1], alo[mt][2], alo[mt][3],
                                 bhi[pp][t * 2], bhi[pp][t * 2 + 1]);
                    }
                }
            }

            const int nx = s + NS - 1;
            if (nx < nIter)
                issue(sbase + (uint32_t)(nx & (NS - 1)) * ST_BYTES,
                      Ah, Al, sA, Bh, Bl, sB, nx * 16, tid);
            CPCOMMIT();
        }
        __syncthreads();
    }
};

// ---------------------------------------------------------------------------
// Split fp32 tensors into bf16 hi/lo planes
// ---------------------------------------------------------------------------
__global__ __launch_bounds__(256) void split_inputs(
    const float* __restrict__ a0, const float* __restrict__ a1,
    const float* __restrict__ a2,
    __nv_bfloat16* __restrict__ h0, __nv_bfloat16* __restrict__ l0,
    __nv_bfloat16* __restrict__ h1, __nv_bfloat16* __restrict__ l1,
    __nv_bfloat16* __restrict__ h2, __nv_bfloat16* __restrict__ l2)
{
    const int z = blockIdx.y;
    const float* s = (z == 0) ? a0 : (z == 1) ? a1 : a2;
    __nv_bfloat16* H = (z == 0) ? h0 : (z == 1) ? h1 : h2;
    __nv_bfloat16* L = (z == 0) ? l0 : (z == 1) ? l1 : l2;
    const size_t i = ((size_t)blockIdx.x * 256 + threadIdx.x) * 4;
    float4 f = *(const float4*)(s + i);
    uint2 hi, lo;
    split4(f, hi, lo);
    *(uint2*)(H + i) = hi;
    *(uint2*)(L + i) = lo;
}

__global__ __launch_bounds__(256) void split_weights(
    const float* __restrict__ w0, const float* __restrict__ w1,
    const float* __restrict__ w2, const float* __restrict__ w3,
    __nv_bfloat16* __restrict__ wh, __nv_bfloat16* __restrict__ wl)
{
    const int z = blockIdx.y;
    const float* s = (z == 0) ? w0 : (z == 1) ? w1 : (z == 2) ? w2 : w3;
    const size_t base = (size_t)z * DD * DD;
    const size_t i = ((size_t)blockIdx.x * 256 + threadIdx.x) * 4;
    float4 f = *(const float4*)(s + i);
    uint2 hi, lo;
    split4(f, hi, lo);
    *(uint2*)(wh + base + i) = hi;
    *(uint2*)(wl + base + i) = lo;
}

// ---------------------------------------------------------------------------
// Batched Q/K/V projection: z=0 -> q planes, z=1 -> k planes, z=2 -> v fp32
// ---------------------------------------------------------------------------
__global__ __launch_bounds__(256) void proj_qkv(
    const __nv_bfloat16* __restrict__ qih, const __nv_bfloat16* __restrict__ qil,
    const __nv_bfloat16* __restrict__ kih, const __nv_bfloat16* __restrict__ kil,
    const __nv_bfloat16* __restrict__ vih, const __nv_bfloat16* __restrict__ vil,
    const __nv_bfloat16* __restrict__ wh, const __nv_bfloat16* __restrict__ wl,
    const float* __restrict__ bq, const float* __restrict__ bk,
    const float* __restrict__ bv,
    __nv_bfloat16* __restrict__ qh, __nv_bfloat16* __restrict__ ql,
    __nv_bfloat16* __restrict__ kh, __nv_bfloat16* __restrict__ kl,
    float* __restrict__ v)
{
    extern __shared__ char dsm[];
    const uint32_t sbase = smem_u32(dsm);
    const int tid  = threadIdx.x;
    const int lane = tid & 31;
    const int wid  = tid >> 5;
    const int wm   = wid >> 2;
    const int wn   = wid & 3;
    const int bn   = blockIdx.x;
    const int bm   = blockIdx.y;
    const int z    = blockIdx.z;

    const __nv_bfloat16* Ah = (z == 0) ? qih : (z == 1) ? kih : vih;
    const __nv_bfloat16* Al = (z == 0) ? qil : (z == 1) ? kil : vil;
    const float* bias = (z == 0) ? bq : (z == 1) ? bk : bv;
    const size_t wbase = (size_t)z * DD * DD;

    MmaB16v2 core;
    core.run(sbase,
             Ah + (size_t)(bm * 128) * DD, Al + (size_t)(bm * 128) * DD, DD,
             wh + wbase + (size_t)(bn * 128) * DD,
             wl + wbase + (size_t)(bn * 128) * DD, DD,
             DD / 16, tid);

    #pragma unroll
    for (int mt = 0; mt < 4; mt++) {
        const int row = bm * 128 + wm * 64 + mt * 16 + (lane >> 2);
        #pragma unroll
        for (int nt = 0; nt < 4; nt++) {
            const int col = bn * 128 + wn * 32 + nt * 8 + (lane & 3) * 2;
            const float b0 = bias[col], b1 = bias[col + 1];
            const float v0 = core.acc[mt][nt][0] + b0;
            const float v1 = core.acc[mt][nt][1] + b1;
            const float v2 = core.acc[mt][nt][2] + b0;
            const float v3 = core.acc[mt][nt][3] + b1;
            if (z == 2) {
                *(float2*)(v + (size_t)row * DD + col) = make_float2(v0, v1);
                *(float2*)(v + (size_t)(row + 8) * DD + col) = make_float2(v2, v3);
            } else {
                __nv_bfloat16* H = (z == 0) ? qh : kh;
                __nv_bfloat16* L = (z == 0) ? ql : kl;
                __nv_bfloat16 h0 = __float2bfloat16_rn(v0);
                __nv_bfloat16 h1 = __float2bfloat16_rn(v1);
                __nv_bfloat16 h2 = __float2bfloat16_rn(v2);
                __nv_bfloat16 h3 = __float2bfloat16_rn(v3);
                *(uint32_t*)(H + (size_t)row * DD + col) = pack_bf2(h0, h1);
                *(uint32_t*)(L + (size_t)row * DD + col) = pack_bf2(
                    __float2bfloat16_rn(v0 - __bfloat162float(h0)),
                    __float2bfloat16_rn(v1 - __bfloat162float(h1)));
                *(uint32_t*)(H + (size_t)(row + 8) * DD + col) = pack_bf2(h2, h3);
                *(uint32_t*)(L + (size_t)(row + 8) * DD + col) = pack_bf2(
                    __float2bfloat16_rn(v2 - __bfloat162float(h2)),
                    __float2bfloat16_rn(v3 - __bfloat162float(h3)));
            }
        }
    }
}

// ---------------------------------------------------------------------------
// Final GEMM: out = x @ Wo^T + bo
// ---------------------------------------------------------------------------
__global__ __launch_bounds__(256) void gemm_b16(
    const __nv_bfloat16* __restrict__ Ah, const __nv_bfloat16* __restrict__ Al,
    const __nv_bfloat16* __restrict__ Wh, const __nv_bfloat16* __restrict__ Wl,
    const float* __restrict__ bias, float* __restrict__ C)
{
    extern __shared__ char dsm[];
    const uint32_t sbase = smem_u32(dsm);
    const int tid  = threadIdx.x;
    const int lane = tid & 31;
    const int wid  = tid >> 5;
    const int wm   = wid >> 2;
    const int wn   = wid & 3;
    const int bn   = blockIdx.x;
    const int bm   = blockIdx.y;

    MmaB16v2 core;
    core.run(sbase,
             Ah + (size_t)(bm * 128) * DD, Al + (size_t)(bm * 128) * DD, DD,
             Wh + (size_t)(bn * 128) * DD, Wl + (size_t)(bn * 128) * DD, DD,
             DD / 16, tid);

    #pragma unroll
    for (int mt = 0; mt < 4; mt++) {
        const int row = bm * 128 + wm * 64 + mt * 16 + (lane >> 2);
        #pragma unroll
        for (int nt = 0; nt < 4; nt++) {
            const int col = bn * 128 + wn * 32 + nt * 8 + (lane & 3) * 2;
            const float b0 = bias[col], b1 = bias[col + 1];
            float2 o0, o1;
            o0.x = core.acc[mt][nt][0] + b0; o0.y = core.acc[mt][nt][1] + b1;
            o1.x = core.acc[mt][nt][2] + b0; o1.y = core.acc[mt][nt][3] + b1;
            *(float2*)(C + (size_t)row * DD + col) = o0;
            *(float2*)(C + (size_t)(row + 8) * DD + col) = o1;
        }
    }
}

// ---------------------------------------------------------------------------
// Scores+exp from q/k planes; causal; row-sum partials.
// ---------------------------------------------------------------------------
__global__ __launch_bounds__(256) void scores_exp_kernel(
    const __nv_bfloat16* __restrict__ qh, const __nv_bfloat16* __restrict__ ql,
    const __nv_bfloat16* __restrict__ kh, const __nv_bfloat16* __restrict__ kl,
    float* __restrict__ attn, float* __restrict__ rpart)
{
    const int bn = blockIdx.x;
    const int bm = blockIdx.y;
    const int bh = blockIdx.z;
    float* out = attn + (size_t)bh * SS * SS;
    const int tid = threadIdx.x;

    if (bn > bm) {  // fully masked tile: zero-fill
        const int row = bm * 128 + (tid >> 1);
        const int c0  = bn * 128 + (tid & 1) * 64;
        const float4 z = make_float4(0.f, 0.f, 0.f, 0.f);
        #pragma unroll
        for (int c = 0; c < 16; c++)
            *(float4*)(out + (size_t)row * SS + c0 + c * 4) = z;
        return;
    }

    extern __shared__ char dsm[];
    __shared__ float rs[128][4];
    const uint32_t sbase = smem_u32(dsm);
    const int lane = tid & 31;
    const int wid  = tid >> 5;
    const int wm   = wid >> 2;
    const int wn   = wid & 3;
    const int b = bh / HH, h = bh % HH;

    const size_t aoff = (size_t)(b * SS + bm * 128) * DD + h * DK;
    const size_t boff = (size_t)(b * SS + bn * 128) * DD + h * DK;

    MmaB16v2 core;
    core.run(sbase, qh + aoff, ql + aoff, DD, kh + boff, kl + boff, DD,
             DK / 16, tid);

    float rsum[4][2];
    #pragma unroll
    for (int mt = 0; mt < 4; mt++) { rsum[mt][0] = 0.f; rsum[mt][1] = 0.f; }

    #pragma unroll
    for (int mt = 0; mt < 4; mt++) {
        const int r0 = bm * 128 + wm * 64 + mt * 16 + (lane >> 2);
        const int r1 = r0 + 8;
        #pragma unroll
        for (int nt = 0; nt < 4; nt++) {
            const int col = bn * 128 + wn * 32 + nt * 8 + (lane & 3) * 2;
            float e0 = (col     <= r0) ? __expf(core.acc[mt][nt][0] * SCALE) : 0.f;
            float e1 = (col + 1 <= r0) ? __expf(core.acc[mt][nt][1] * SCALE) : 0.f;
            float e2 = (col     <= r1) ? __expf(core.acc[mt][nt][2] * SCALE) : 0.f;
            float e3 = (col + 1 <= r1) ? __expf(core.acc[mt][nt][3] * SCALE) : 0.f;
            rsum[mt][0] += e0 + e1;
            rsum[mt][1] += e2 + e3;
            *(float2*)(out + (size_t)r0 * SS + col) = make_float2(e0, e1);
            *(float2*)(out + (size_t)r1 * SS + col) = make_float2(e2, e3);
        }
    }

    #pragma unroll
    for (int mt = 0; mt < 4; mt++) {
        #pragma unroll
        for (int hf = 0; hf < 2; hf++) {
            float vv = rsum[mt][hf];
            vv += __shfl_xor_sync(0xffffffffu, vv, 1);
            vv += __shfl_xor_sync(0xffffffffu, vv, 2);
            if ((lane & 3) == 0) {
                const int lrow = wm * 64 + mt * 16 + hf * 8 + (lane >> 2);
                rs[lrow][wn] = vv;
            }
        }
    }
    __syncthreads();
    if (tid < 128) {
        const float p = rs[tid][0] + rs[tid][1] + rs[tid][2] + rs[tid][3];
        rpart[((size_t)bh * SS + bm * 128 + tid) * 16 + bn] = p;
    }
}

// ---------------------------------------------------------------------------
// Normalize rows; write fp32 attn AND bf16 hi/lo P-planes (zero-padded to
// the 128-col diagonal boundary so AV can consume whole tiles).
// ---------------------------------------------------------------------------
__global__ __launch_bounds__(256) void normalize_kernel(
    float* __restrict__ attn, const float* __restrict__ rpart,
    __nv_bfloat16* __restrict__ ph, __nv_bfloat16* __restrict__ pl)
{
    const int blk = blockIdx.x;           // bh*SS + s
    const int s   = blk & (SS - 1);
    __shared__ float sinv;
    if (threadIdx.x == 0) {
        const float* p = rpart + (size_t)blk * 16;
        const int nb = (s >> 7) + 1;
        float sum = 0.f;
        for (int i = 0; i < nb; i++) sum += p[i];
        sinv = 1.0f / sum;
    }
    __syncthreads();
    const float inv = sinv;
    float* row = attn + (size_t)blk * SS;
    __nv_bfloat16* prh = ph + (size_t)blk * SS;
    __nv_bfloat16* prl = pl + (size_t)blk * SS;
    const int limit = ((s >> 7) + 1) * 128;
    for (int j = threadIdx.x * 4; j < limit; j += 1024) {
        float4 v = *(float4*)(row + j);
        v.x *= inv; v.y *= inv; v.z *= inv; v.w *= inv;
        *(float4*)(row + j) = v;
        uint2 hi, lo;
        split4(v, hi, lo);
        *(uint2*)(prh + j) = hi;
        *(uint2*)(prl + j) = lo;
    }
}

// ---------------------------------------------------------------------------
// Transpose V per head into bf16 hi/lo planes: vt[bh][d][s]
// ---------------------------------------------------------------------------
__global__ __launch_bounds__(256) void transpose_v(
    const float* __restrict__ v,
    __nv_bfloat16* __restrict__ vth, __nv_bfloat16* __restrict__ vtl)
{
    __shared__ float t[32][33];
    const int bh = blockIdx.z, b = bh / HH, h = bh % HH;
    const int s0 = blockIdx.x * 32, d0 = blockIdx.y * 32;
    const int tx = threadIdx.x & 31, ty = threadIdx.x >> 5;
    #pragma unroll
    for (int i = 0; i < 4; i++)
        t[ty + i * 8][tx] =
            v[(size_t)(b * SS + s0 + ty + i * 8) * DD + h * DK + d0 + tx];
    __syncthreads();
    #pragma unroll
    for (int i = 0; i < 4; i++) {
        const float f = t[tx][ty + i * 8];
        const __nv_bfloat16 hh = __float2bfloat16_rn(f);
        const __nv_bfloat16 ll = __float2bfloat16_rn(f - __bfloat162float(hh));
        const size_t idx = (size_t)bh * DK * SS + (size_t)(d0 + ty + i * 8) * SS
                         + s0 + tx;
        vth[idx] = hh;
        vtl[idx] = ll;
    }
}

// ---------------------------------------------------------------------------
// AV: x = P @ V from P planes (normalized) and V^T planes.
// ---------------------------------------------------------------------------
__global__ __launch_bounds__(256) void av_mma_kernel(
    const __nv_bfloat16* __restrict__ ph, const __nv_bfloat16* __restrict__ pl,
    const __nv_bfloat16* __restrict__ vth, const __nv_bfloat16* __restrict__ vtl,
    __nv_bfloat16* __restrict__ xh, __nv_bfloat16* __restrict__ xl)
{
    extern __shared__ char dsm[];
    const uint32_t sbase = smem_u32(dsm);
    const int bm = blockIdx.x;
    const int bh = blockIdx.y;
    const int b = bh / HH, h = bh % HH;
    const int tid  = threadIdx.x;
    const int lane = tid & 31;
    const int wid  = tid >> 5;
    const int wm   = wid >> 2;
    const int wn   = wid & 3;

    const size_t aoff = (size_t)bh * SS * SS + (size_t)(bm * 128) * SS;
    const size_t boff = (size_t)bh * DK * SS;

    MmaB16v2 core;
    core.run(sbase, ph + aoff, pl + aoff, SS, vth + boff, vtl + boff, SS,
             (bm + 1) * 8, tid);

    #pragma unroll
    for (int mt = 0; mt < 4; mt++) {
        const int row = bm * 128 + wm * 64 + mt * 16 + (lane >> 2);
        #pragma unroll
        for (int nt = 0; nt < 4; nt++) {
            const int col = wn * 32 + nt * 8 + (lane & 3) * 2;
            const float v0 = core.acc[mt][nt][0];
            const float v1 = core.acc[mt][nt][1];
            const float v2 = core.acc[mt][nt][2];
            const float v3 = core.acc[mt][nt][3];
            __nv_bfloat16 h0 = __float2bfloat16_rn(v0);
            __nv_bfloat16 h1 = __float2bfloat16_rn(v1);
            __nv_bfloat16 h2 = __float2bfloat16_rn(v2);
            __nv_bfloat16 h3 = __float2bfloat16_rn(v3);
            const size_t o0 = (size_t)(b * SS + row) * DD + h * DK + col;
            const size_t o1 = (size_t)(b * SS + row + 8) * DD + h * DK + col;
            *(uint32_t*)(xh + o0) = pack_bf2(h0, h1);
            *(uint32_t*)(xl + o0) = pack_bf2(
                __float2bfloat16_rn(v0 - __bfloat162float(h0)),
                __float2bfloat16_rn(v1 - __bfloat162float(h1)));
            *(uint32_t*)(xh + o1) = pack_bf2(h2, h3);
            *(uint32_t*)(xl + o1) = pack_bf2(
                __float2bfloat16_rn(v2 - __bfloat162float(h2)),
                __float2bfloat16_rn(v3 - __bfloat162float(h3)));
        }
    }
}

// ---------------------------------------------------------------------------
extern "C" void kernel_launch(void* const* d_in, const int* in_sizes, int n_in,
                              void* d_out, int out_size)
{
    const float* query = (const float*)d_in[0];
    const float* key   = (const float*)d_in[1];
    const float* value = (const float*)d_in[2];
    const float* Wq = (const float*)d_in[3];
    const float* bq = (const float*)d_in[4];
    const float* Wk = (const float*)d_in[5];
    const float* bk = (const float*)d_in[6];
    const float* Wv = (const float*)d_in[7];
    const float* bv = (const float*)d_in[8];
    const float* Wo = (const float*)d_in[9];
    const float* bo = (const float*)d_in[10];

    float* out  = (float*)d_out;                       // [4096, 2048]
    float* attn = out + (size_t)MTOK * DD;             // [32, 2048, 2048]

    float *v, *rpart;
    __nv_bfloat16 *qih, *qil, *kih, *kil, *vih, *vil, *wh, *wl;
    __nv_bfloat16 *qh, *ql, *kh, *kl, *xh, *xl, *vth, *vtl, *ph, *pl;
    cudaGetSymbolAddress((void**)&v, g_v);
    cudaGetSymbolAddress((void**)&rpart, g_rpart);
    cudaGetSymbolAddress((void**)&qih, g_qih);
    cudaGetSymbolAddress((void**)&qil, g_qil);
    cudaGetSymbolAddress((void**)&kih, g_kih);
    cudaGetSymbolAddress((void**)&kil, g_kil);
    cudaGetSymbolAddress((void**)&vih, g_vih);
    cudaGetSymbolAddress((void**)&vil, g_vil);
    cudaGetSymbolAddress((void**)&wh, g_wh);
    cudaGetSymbolAddress((void**)&wl, g_wl);
    cudaGetSymbolAddress((void**)&qh, g_qh);
    cudaGetSymbolAddress((void**)&ql, g_ql);
    cudaGetSymbolAddress((void**)&kh, g_kh);
    cudaGetSymbolAddress((void**)&kl, g_kl);
    cudaGetSymbolAddress((void**)&xh, g_xh);
    cudaGetSymbolAddress((void**)&xl, g_xl);
    cudaGetSymbolAddress((void**)&vth, g_vth);
    cudaGetSymbolAddress((void**)&vtl, g_vtl);
    cudaGetSymbolAddress((void**)&ph, g_ph);
    cudaGetSymbolAddress((void**)&pl, g_pl);

    static bool attrs_set = false;
    if (!attrs_set) {
        cudaFuncSetAttribute(proj_qkv,
            cudaFuncAttributeMaxDynamicSharedMemorySize, DSMEM_TOTAL);
        cudaFuncSetAttribute(gemm_b16,
            cudaFuncAttributeMaxDynamicSharedMemorySize, DSMEM_TOTAL);
        cudaFuncSetAttribute(scores_exp_kernel,
            cudaFuncAttributeMaxDynamicSharedMemorySize, DSMEM_TOTAL);
        cudaFuncSetAttribute(av_mma_kernel,
            cudaFuncAttributeMaxDynamicSharedMemorySize, DSMEM_TOTAL);
        attrs_set = true;
    }

    // 1. Split inputs and weights into bf16 planes
    dim3 gsi((MTOK * DD) / (256 * 4), 3);
    split_inputs<<<gsi, 256>>>(query, key, value,
                               qih, qil, kih, kil, vih, vil);
    dim3 gsw((DD * DD) / (256 * 4), 4);
    split_weights<<<gsw, 256>>>(Wq, Wk, Wv, Wo, wh, wl);

    // 2. Batched Q/K/V projections
    dim3 gproj(DD / 128, MTOK / 128, 3);
    proj_qkv<<<gproj, 256, DSMEM_TOTAL>>>(
        qih, qil, kih, kil, vih, vil, wh, wl, bq, bk, bv,
        qh, ql, kh, kl, v);

    // 3. V transpose -> planes
    dim3 gtr(SS / 32, DK / 32, BB * HH);
    transpose_v<<<gtr, 256>>>(v, vth, vtl);

    // 4. Scores + exp (+ partial row sums)
    dim3 gsc(SS / 128, SS / 128, BB * HH);
    scores_exp_kernel<<<gsc, 256, DSMEM_TOTAL>>>(qh, ql, kh, kl, attn, rpart);

    // 5. Normalize (+ emit P planes)
    normalize_kernel<<<BB * HH * SS, 256>>>(attn, rpart, ph, pl);

    // 6. AV from P planes
    dim3 gav(SS / 128, BB * HH);
    av_mma_kernel<<<gav, 256, DSMEM_TOTAL>>>(ph, pl, vth, vtl, xh, xl);

    // 7. Output projection
    dim3 gout(DD / 128, MTOK / 128);
    gemm_b16<<<gout, 256, DSMEM_TOTAL>>>(
        xh, xl, wh + (size_t)3 * DD * DD, wl + (size_t)3 * DD * DD, bo, out);
}

// round 8
// speedup vs baseline: 2.5283x; 1.0411x over previous
#include <cuda_runtime.h>
#include <cuda_bf16.h>
#include <cstdint>
#include <math.h>

// ---------------------------------------------------------------------------
// Problem constants
// ---------------------------------------------------------------------------
#define BB   2
#define SS   2048
#define DD   2048
#define HH   16
#define DK   128
#define MTOK (BB * SS)          // 4096 tokens
#define SCALE 0.08838834764831845f  // 1/sqrt(128)

// Scratch (device globals; no cudaMalloc allowed)
static __device__ float g_v [(size_t)MTOK * DD];
static __device__ float g_rpart[(size_t)BB * HH * SS * 16];
static __device__ float g_inv[(size_t)BB * HH * SS];
// bf16 hi/lo planes
static __device__ __nv_bfloat16 g_qih[(size_t)MTOK * DD], g_qil[(size_t)MTOK * DD];
static __device__ __nv_bfloat16 g_kih[(size_t)MTOK * DD], g_kil[(size_t)MTOK * DD];
static __device__ __nv_bfloat16 g_vih[(size_t)MTOK * DD], g_vil[(size_t)MTOK * DD];
static __device__ __nv_bfloat16 g_wh[(size_t)4 * DD * DD], g_wl[(size_t)4 * DD * DD];
static __device__ __nv_bfloat16 g_qh[(size_t)MTOK * DD], g_ql[(size_t)MTOK * DD];
static __device__ __nv_bfloat16 g_kh[(size_t)MTOK * DD], g_kl[(size_t)MTOK * DD];
static __device__ __nv_bfloat16 g_xh[(size_t)MTOK * DD], g_xl[(size_t)MTOK * DD];
static __device__ __nv_bfloat16 g_vth[(size_t)BB * HH * DK * SS];
static __device__ __nv_bfloat16 g_vtl[(size_t)BB * HH * DK * SS];
// Unnormalized-E planes
static __device__ __nv_bfloat16 g_eh[(size_t)BB * HH * SS * SS];
static __device__ __nv_bfloat16 g_el[(size_t)BB * HH * SS * SS];

// ---------------------------------------------------------------------------
// PTX helpers
// ---------------------------------------------------------------------------
#define LDSM_X4(r0, r1, r2, r3, addr) \
    asm volatile("ldmatrix.sync.aligned.m8n8.x4.shared.b16 {%0,%1,%2,%3}, [%4];" \
        : "=r"(r0), "=r"(r1), "=r"(r2), "=r"(r3) : "r"(addr))

#define MMA16816(c, a0, a1, a2, a3, b0, b1) \
    asm volatile("mma.sync.aligned.m16n8k16.row.col.f32.bf16.bf16.f32 " \
        "{%0,%1,%2,%3}, {%4,%5,%6,%7}, {%8,%9}, {%0,%1,%2,%3};" \
        : "+f"((c)[0]), "+f"((c)[1]), "+f"((c)[2]), "+f"((c)[3]) \
        : "r"(a0), "r"(a1), "r"(a2), "r"(a3), "r"(b0), "r"(b1))

#define CP16(dst, src) \
    asm volatile("cp.async.cg.shared.global [%0], [%1], 16;" \
        :: "r"(dst), "l"(src))
#define CPCOMMIT() asm volatile("cp.async.commit_group;" ::: "memory")
#define CPWAIT2()  asm volatile("cp.async.wait_group 2;" ::: "memory")

__device__ __forceinline__ uint32_t smem_u32(const void* p) {
    uint32_t a;
    asm("{ .reg .u64 t; cvta.to.shared.u64 t, %1; cvt.u32.u64 %0, t; }"
        : "=r"(a) : "l"(p));
    return a;
}

__device__ __forceinline__ uint32_t pack_bf2(__nv_bfloat16 a, __nv_bfloat16 b) {
    return (uint32_t)__bfloat16_as_ushort(a) |
           ((uint32_t)__bfloat16_as_ushort(b) << 16);
}

__device__ __forceinline__ void split4(const float4 f, uint2& hi, uint2& lo) {
    __nv_bfloat16 h0 = __float2bfloat16_rn(f.x);
    __nv_bfloat16 h1 = __float2bfloat16_rn(f.y);
    __nv_bfloat16 h2 = __float2bfloat16_rn(f.z);
    __nv_bfloat16 h3 = __float2bfloat16_rn(f.w);
    __nv_bfloat16 l0 = __float2bfloat16_rn(f.x - __bfloat162float(h0));
    __nv_bfloat16 l1 = __float2bfloat16_rn(f.y - __bfloat162float(h1));
    __nv_bfloat16 l2 = __float2bfloat16_rn(f.z - __bfloat162float(h2));
    __nv_bfloat16 l3 = __float2bfloat16_rn(f.w - __bfloat162float(h3));
    hi.x = pack_bf2(h0, h1); hi.y = pack_bf2(h2, h3);
    lo.x = pack_bf2(l0, l1); lo.y = pack_bf2(l2, l3);
}

// ---------------------------------------------------------------------------
// MmaB16v2: 128x128 tile, K-chunk 16, 4-stage cp.async pipeline.
// ---------------------------------------------------------------------------
#define NS 4
#define RS2 48
#define ST_AHI 0
#define ST_ALO 6144
#define ST_BHI 12288
#define ST_BLO 18432
#define ST_BYTES 24576
#define DSMEM_TOTAL (NS * ST_BYTES)   // 98304

struct MmaB16v2 {
    float acc[4][4][4];

    __device__ __forceinline__ static void issue(
        uint32_t sb,
        const __nv_bfloat16* Ah, const __nv_bfloat16* Al, size_t sA,
        const __nv_bfloat16* Bh, const __nv_bfloat16* Bl, size_t sB,
        int k0, int tid)
    {
        const int row  = tid >> 1;
        const int half = tid & 1;
        const uint32_t so = (uint32_t)row * RS2 + half * 16;
        const size_t oA = (size_t)row * sA + k0 + half * 8;
        const size_t oB = (size_t)row * sB + k0 + half * 8;
        CP16(sb + ST_AHI + so, Ah + oA);
        CP16(sb + ST_ALO + so, Al + oA);
        CP16(sb + ST_BHI + so, Bh + oB);
        CP16(sb + ST_BLO + so, Bl + oB);
    }

    __device__ __forceinline__ void run(
        uint32_t sbase,
        const __nv_bfloat16* Ah, const __nv_bfloat16* Al, size_t sA,
        const __nv_bfloat16* Bh, const __nv_bfloat16* Bl, size_t sB,
        const int nIter, const int tid)
    {
        const int lane = tid & 31;
        const int wid  = tid >> 5;
        const int wm   = wid >> 2;
        const int wn   = wid & 3;

        #pragma unroll
        for (int i = 0; i < 4; i++)
            #pragma unroll
            for (int j = 0; j < 4; j++)
                #pragma unroll
                for (int c = 0; c < 4; c++) acc[i][j][c] = 0.0f;

        const uint32_t aAddr = sbase + ST_AHI
            + (uint32_t)(wm * 64 + (lane & 15)) * RS2 + (lane >> 4) * 16;
        const uint32_t bAddr = sbase + ST_BHI
            + (uint32_t)(wn * 32 + (lane & 7) + ((lane >> 4) & 1) * 8) * RS2
            + ((lane >> 3) & 1) * 16;

        #pragma unroll
        for (int p = 0; p < NS - 1; p++) {
            if (p < nIter)
                issue(sbase + p * ST_BYTES, Ah, Al, sA, Bh, Bl, sB, p * 16, tid);
            CPCOMMIT();
        }

        for (int s = 0; s < nIter; s++) {
            CPWAIT2();
            __syncthreads();

            const uint32_t bo = (uint32_t)(s & (NS - 1)) * ST_BYTES;
            uint32_t ahi[4][4], alo[4][4];
            uint32_t bhi[2][4], blo[2][4];
            #pragma unroll
            for (int mt = 0; mt < 4; mt++) {
                const uint32_t a = aAddr + bo + mt * (16 * RS2);
                LDSM_X4(ahi[mt][0], ahi[mt][1], ahi[mt][2], ahi[mt][3], a);
                LDSM_X4(alo[mt][0], alo[mt][1], alo[mt][2], alo[mt][3],
                        a + (ST_ALO - ST_AHI));
            }
            #pragma unroll
            for (int pp = 0; pp < 2; pp++) {
                const uint32_t b = bAddr + bo + pp * (16 * RS2);
                LDSM_X4(bhi[pp][0], bhi[pp][1], bhi[pp][2], bhi[pp][3], b);
                LDSM_X4(blo[pp][0], blo[pp][1], blo[pp][2], blo[pp][3],
                        b + (ST_BLO - ST_BHI));
            }
            #pragma unroll
            for (int mt = 0; mt < 4; mt++) {
                #pragma unroll
                for (int pp = 0; pp < 2; pp++) {
                    #pragma unroll
                    for (int t = 0; t < 2; t++) {
                        const int nt = pp * 2 + t;
                        MMA16816(acc[mt][nt],
                                 ahi[mt][0], ahi[mt][1], ahi[mt][2], ahi[mt][3],
                                 bhi[pp][t * 2], bhi[pp][t * 2 + 1]);
                        MMA16816(acc[mt][nt],
                                 ahi[mt][0], ahi[mt][1], ahi[mt][2], ahi[mt][3],
                                 blo[pp][t * 2], blo[pp][t * 2 + 1]);
                        MMA16816(acc[mt][nt],
                                 alo[mt][0], alo[mt][1], alo[mt][2], alo[mt][3],
                                 bhi[pp][t * 2], bhi[pp][t * 2 + 1]);
                    }
                }
            }

            const int nx = s + NS - 1;
            if (nx < nIter)
                issue(sbase + (uint32_t)(nx & (NS - 1)) * ST_BYTES,
                      Ah, Al, sA, Bh, Bl, sB, nx * 16, tid);
            CPCOMMIT();
        }
        __syncthreads();
    }
};

// ---------------------------------------------------------------------------
// Split fp32 tensors into bf16 hi/lo planes
// ---------------------------------------------------------------------------
__global__ __launch_bounds__(256) void split_inputs(
    const float* __restrict__ a0, const float* __restrict__ a1,
    const float* __restrict__ a2,
    __nv_bfloat16* __restrict__ h0, __nv_bfloat16* __restrict__ l0,
    __nv_bfloat16* __restrict__ h1, __nv_bfloat16* __restrict__ l1,
    __nv_bfloat16* __restrict__ h2, __nv_bfloat16* __restrict__ l2)
{
    const int z = blockIdx.y;
    const float* s = (z == 0) ? a0 : (z == 1) ? a1 : a2;
    __nv_bfloat16* H = (z == 0) ? h0 : (z == 1) ? h1 : h2;
    __nv_bfloat16* L = (z == 0) ? l0 : (z == 1) ? l1 : l2;
    const size_t i = ((size_t)blockIdx.x * 256 + threadIdx.x) * 4;
    float4 f = *(const float4*)(s + i);
    uint2 hi, lo;
    split4(f, hi, lo);
    *(uint2*)(H + i) = hi;
    *(uint2*)(L + i) = lo;
}

__global__ __launch_bounds__(256) void split_weights(
    const float* __restrict__ w0, const float* __restrict__ w1,
    const float* __restrict__ w2, const float* __restrict__ w3,
    __nv_bfloat16* __restrict__ wh, __nv_bfloat16* __restrict__ wl)
{
    const int z = blockIdx.y;
    const float* s = (z == 0) ? w0 : (z == 1) ? w1 : (z == 2) ? w2 : w3;
    const size_t base = (size_t)z * DD * DD;
    const size_t i = ((size_t)blockIdx.x * 256 + threadIdx.x) * 4;
    float4 f = *(const float4*)(s + i);
    uint2 hi, lo;
    split4(f, hi, lo);
    *(uint2*)(wh + base + i) = hi;
    *(uint2*)(wl + base + i) = lo;
}

// ---------------------------------------------------------------------------
// Batched Q/K/V projection: z=0 -> q planes, z=1 -> k planes, z=2 -> v fp32
// ---------------------------------------------------------------------------
__global__ __launch_bounds__(256) void proj_qkv(
    const __nv_bfloat16* __restrict__ qih, const __nv_bfloat16* __restrict__ qil,
    const __nv_bfloat16* __restrict__ kih, const __nv_bfloat16* __restrict__ kil,
    const __nv_bfloat16* __restrict__ vih, const __nv_bfloat16* __restrict__ vil,
    const __nv_bfloat16* __restrict__ wh, const __nv_bfloat16* __restrict__ wl,
    const float* __restrict__ bq, const float* __restrict__ bk,
    const float* __restrict__ bv,
    __nv_bfloat16* __restrict__ qh, __nv_bfloat16* __restrict__ ql,
    __nv_bfloat16* __restrict__ kh, __nv_bfloat16* __restrict__ kl,
    float* __restrict__ v)
{
    extern __shared__ char dsm[];
    const uint32_t sbase = smem_u32(dsm);
    const int tid  = threadIdx.x;
    const int lane = tid & 31;
    const int wid  = tid >> 5;
    const int wm   = wid >> 2;
    const int wn   = wid & 3;
    const int bn   = blockIdx.x;
    const int bm   = blockIdx.y;
    const int z    = blockIdx.z;

    const __nv_bfloat16* Ah = (z == 0) ? qih : (z == 1) ? kih : vih;
    const __nv_bfloat16* Al = (z == 0) ? qil : (z == 1) ? kil : vil;
    const float* bias = (z == 0) ? bq : (z == 1) ? bk : bv;
    const size_t wbase = (size_t)z * DD * DD;

    MmaB16v2 core;
    core.run(sbase,
             Ah + (size_t)(bm * 128) * DD, Al + (size_t)(bm * 128) * DD, DD,
             wh + wbase + (size_t)(bn * 128) * DD,
             wl + wbase + (size_t)(bn * 128) * DD, DD,
             DD / 16, tid);

    #pragma unroll
    for (int mt = 0; mt < 4; mt++) {
        const int row = bm * 128 + wm * 64 + mt * 16 + (lane >> 2);
        #pragma unroll
        for (int nt = 0; nt < 4; nt++) {
            const int col = bn * 128 + wn * 32 + nt * 8 + (lane & 3) * 2;
            const float b0 = bias[col], b1 = bias[col + 1];
            const float v0 = core.acc[mt][nt][0] + b0;
            const float v1 = core.acc[mt][nt][1] + b1;
            const float v2 = core.acc[mt][nt][2] + b0;
            const float v3 = core.acc[mt][nt][3] + b1;
            if (z == 2) {
                *(float2*)(v + (size_t)row * DD + col) = make_float2(v0, v1);
                *(float2*)(v + (size_t)(row + 8) * DD + col) = make_float2(v2, v3);
            } else {
                __nv_bfloat16* H = (z == 0) ? qh : kh;
                __nv_bfloat16* L = (z == 0) ? ql : kl;
                __nv_bfloat16 h0 = __float2bfloat16_rn(v0);
                __nv_bfloat16 h1 = __float2bfloat16_rn(v1);
                __nv_bfloat16 h2 = __float2bfloat16_rn(v2);
                __nv_bfloat16 h3 = __float2bfloat16_rn(v3);
                *(uint32_t*)(H + (size_t)row * DD + col) = pack_bf2(h0, h1);
                *(uint32_t*)(L + (size_t)row * DD + col) = pack_bf2(
                    __float2bfloat16_rn(v0 - __bfloat162float(h0)),
                    __float2bfloat16_rn(v1 - __bfloat162float(h1)));
                *(uint32_t*)(H + (size_t)(row + 8) * DD + col) = pack_bf2(h2, h3);
                *(uint32_t*)(L + (size_t)(row + 8) * DD + col) = pack_bf2(
                    __float2bfloat16_rn(v2 - __bfloat162float(h2)),
                    __float2bfloat16_rn(v3 - __bfloat162float(h3)));
            }
        }
    }
}

// ---------------------------------------------------------------------------
// Final GEMM: out = x @ Wo^T + bo
// ---------------------------------------------------------------------------
__global__ __launch_bounds__(256) void gemm_b16(
    const __nv_bfloat16* __restrict__ Ah, const __nv_bfloat16* __restrict__ Al,
    const __nv_bfloat16* __restrict__ Wh, const __nv_bfloat16* __restrict__ Wl,
    const float* __restrict__ bias, float* __restrict__ C)
{
    extern __shared__ char dsm[];
    const uint32_t sbase = smem_u32(dsm);
    const int tid  = threadIdx.x;
    const int lane = tid & 31;
    const int wid  = tid >> 5;
    const int wm   = wid >> 2;
    const int wn   = wid & 3;
    const int bn   = blockIdx.x;
    const int bm   = blockIdx.y;

    MmaB16v2 core;
    core.run(sbase,
             Ah + (size_t)(bm * 128) * DD, Al + (size_t)(bm * 128) * DD, DD,
             Wh + (size_t)(bn * 128) * DD, Wl + (size_t)(bn * 128) * DD, DD,
             DD / 16, tid);

    #pragma unroll
    for (int mt = 0; mt < 4; mt++) {
        const int row = bm * 128 + wm * 64 + mt * 16 + (lane >> 2);
        #pragma unroll
        for (int nt = 0; nt < 4; nt++) {
            const int col = bn * 128 + wn * 32 + nt * 8 + (lane & 3) * 2;
            const float b0 = bias[col], b1 = bias[col + 1];
            float2 o0, o1;
            o0.x = core.acc[mt][nt][0] + b0; o0.y = core.acc[mt][nt][1] + b1;
            o1.x = core.acc[mt][nt][2] + b0; o1.y = core.acc[mt][nt][3] + b1;
            *(float2*)(C + (size_t)row * DD + col) = o0;
            *(float2*)(C + (size_t)(row + 8) * DD + col) = o1;
        }
    }
}

// ---------------------------------------------------------------------------
// Scores+exp: triangular grid (136 lower tiles per bh). Writes unnormalized
// E planes (bf16 hi/lo) + per-tile row-sum partials. No fp32 E.
// ---------------------------------------------------------------------------
__global__ __launch_bounds__(256) void scores_exp_kernel(
    const __nv_bfloat16* __restrict__ qh, const __nv_bfloat16* __restrict__ ql,
    const __nv_bfloat16* __restrict__ kh, const __nv_bfloat16* __restrict__ kl,
    __nv_bfloat16* __restrict__ eh, __nv_bfloat16* __restrict__ el,
    float* __restrict__ rpart)
{
    const int idx = blockIdx.x;            // 0..135 (lower-triangle tile id)
    int bm = (int)((sqrtf(8.f * idx + 1.f) - 1.f) * 0.5f);
    while ((bm + 1) * (bm + 2) / 2 <= idx) bm++;
    while (bm * (bm + 1) / 2 > idx) bm--;
    const int bn = idx - bm * (bm + 1) / 2;
    const int bh = blockIdx.y;
    const int tid = threadIdx.x;

    extern __shared__ char dsm[];
    __shared__ float rs[128][4];
    const uint32_t sbase = smem_u32(dsm);
    const int lane = tid & 31;
    const int wid  = tid >> 5;
    const int wm   = wid >> 2;
    const int wn   = wid & 3;
    const int b = bh / HH, h = bh % HH;

    const size_t aoff = (size_t)(b * SS + bm * 128) * DD + h * DK;
    const size_t boff = (size_t)(b * SS + bn * 128) * DD + h * DK;

    MmaB16v2 core;
    core.run(sbase, qh + aoff, ql + aoff, DD, kh + boff, kl + boff, DD,
             DK / 16, tid);

    __nv_bfloat16* peh = eh + (size_t)bh * SS * SS;
    __nv_bfloat16* pel = el + (size_t)bh * SS * SS;

    float rsum[4][2];
    #pragma unroll
    for (int mt = 0; mt < 4; mt++) { rsum[mt][0] = 0.f; rsum[mt][1] = 0.f; }

    #pragma unroll
    for (int mt = 0; mt < 4; mt++) {
        const int r0 = bm * 128 + wm * 64 + mt * 16 + (lane >> 2);
        const int r1 = r0 + 8;
        #pragma unroll
        for (int nt = 0; nt < 4; nt++) {
            const int col = bn * 128 + wn * 32 + nt * 8 + (lane & 3) * 2;
            float e0 = (col     <= r0) ? __expf(core.acc[mt][nt][0] * SCALE) : 0.f;
            float e1 = (col + 1 <= r0) ? __expf(core.acc[mt][nt][1] * SCALE) : 0.f;
            float e2 = (col     <= r1) ? __expf(core.acc[mt][nt][2] * SCALE) : 0.f;
            float e3 = (col + 1 <= r1) ? __expf(core.acc[mt][nt][3] * SCALE) : 0.f;
            rsum[mt][0] += e0 + e1;
            rsum[mt][1] += e2 + e3;
            // split to planes
            __nv_bfloat16 h0 = __float2bfloat16_rn(e0);
            __nv_bfloat16 h1 = __float2bfloat16_rn(e1);
            __nv_bfloat16 h2 = __float2bfloat16_rn(e2);
            __nv_bfloat16 h3 = __float2bfloat16_rn(e3);
            *(uint32_t*)(peh + (size_t)r0 * SS + col) = pack_bf2(h0, h1);
            *(uint32_t*)(pel + (size_t)r0 * SS + col) = pack_bf2(
                __float2bfloat16_rn(e0 - __bfloat162float(h0)),
                __float2bfloat16_rn(e1 - __bfloat162float(h1)));
            *(uint32_t*)(peh + (size_t)r1 * SS + col) = pack_bf2(h2, h3);
            *(uint32_t*)(pel + (size_t)r1 * SS + col) = pack_bf2(
                __float2bfloat16_rn(e2 - __bfloat162float(h2)),
                __float2bfloat16_rn(e3 - __bfloat162float(h3)));
        }
    }

    #pragma unroll
    for (int mt = 0; mt < 4; mt++) {
        #pragma unroll
        for (int hf = 0; hf < 2; hf++) {
            float vv = rsum[mt][hf];
            vv += __shfl_xor_sync(0xffffffffu, vv, 1);
            vv += __shfl_xor_sync(0xffffffffu, vv, 2);
            if ((lane & 3) == 0) {
                const int lrow = wm * 64 + mt * 16 + hf * 8 + (lane >> 2);
                rs[lrow][wn] = vv;
            }
        }
    }
    __syncthreads();
    if (tid < 128) {
        const float p = rs[tid][0] + rs[tid][1] + rs[tid][2] + rs[tid][3];
        rpart[((size_t)bh * SS + bm * 128 + tid) * 16 + bn] = p;
    }
}

// ---------------------------------------------------------------------------
// Finalize attn: attn[row] = (Eh+El)*inv for valid prefix, 0 for tail.
// Also stores inv for AV.
// ---------------------------------------------------------------------------
__global__ __launch_bounds__(256) void finalize_attn(
    const __nv_bfloat16* __restrict__ eh, const __nv_bfloat16* __restrict__ el,
    const float* __restrict__ rpart, float* __restrict__ attn,
    float* __restrict__ ginv)
{
    const int blk = blockIdx.x;           // bh*SS + s
    const int s   = blk & (SS - 1);
    __shared__ float sinv;
    if (threadIdx.x == 0) {
        const float* p = rpart + (size_t)blk * 16;
        const int nb = (s >> 7) + 1;
        float sum = 0.f;
        for (int i = 0; i < nb; i++) sum += p[i];
        const float iv = 1.0f / sum;
        sinv = iv;
        ginv[blk] = iv;
    }
    __syncthreads();
    const float inv = sinv;
    const __nv_bfloat16* reh = eh + (size_t)blk * SS;
    const __nv_bfloat16* rel = el + (size_t)blk * SS;
    float* row = attn + (size_t)blk * SS;
    const int limit = ((s >> 7) + 1) * 128;
    for (int j = threadIdx.x * 4; j < SS; j += 1024) {
        float4 o;
        if (j < limit) {
            const __nv_bfloat162 h2 = *(const __nv_bfloat162*)(reh + j);
            const __nv_bfloat162 h3 = *(const __nv_bfloat162*)(reh + j + 2);
            const __nv_bfloat162 l2 = *(const __nv_bfloat162*)(rel + j);
            const __nv_bfloat162 l3 = *(const __nv_bfloat162*)(rel + j + 2);
            o.x = (__bfloat162float(h2.x) + __bfloat162float(l2.x)) * inv;
            o.y = (__bfloat162float(h2.y) + __bfloat162float(l2.y)) * inv;
            o.z = (__bfloat162float(h3.x) + __bfloat162float(l3.x)) * inv;
            o.w = (__bfloat162float(h3.y) + __bfloat162float(l3.y)) * inv;
        } else {
            o = make_float4(0.f, 0.f, 0.f, 0.f);
        }
        *(float4*)(row + j) = o;
    }
}

// ---------------------------------------------------------------------------
// Transpose V per head into bf16 hi/lo planes: vt[bh][d][s]
// ---------------------------------------------------------------------------
__global__ __launch_bounds__(256) void transpose_v(
    const float* __restrict__ v,
    __nv_bfloat16* __restrict__ vth, __nv_bfloat16* __restrict__ vtl)
{
    __shared__ float t[32][33];
    const int bh = blockIdx.z, b = bh / HH, h = bh % HH;
    const int s0 = blockIdx.x * 32, d0 = blockIdx.y * 32;
    const int tx = threadIdx.x & 31, ty = threadIdx.x >> 5;
    #pragma unroll
    for (int i = 0; i < 4; i++)
        t[ty + i * 8][tx] =
            v[(size_t)(b * SS + s0 + ty + i * 8) * DD + h * DK + d0 + tx];
    __syncthreads();
    #pragma unroll
    for (int i = 0; i < 4; i++) {
        const float f = t[tx][ty + i * 8];
        const __nv_bfloat16 hh = __float2bfloat16_rn(f);
        const __nv_bfloat16 ll = __float2bfloat16_rn(f - __bfloat162float(hh));
        const size_t idx = (size_t)bh * DK * SS + (size_t)(d0 + ty + i * 8) * SS
                         + s0 + tx;
        vth[idx] = hh;
        vtl[idx] = ll;
    }
}

// ---------------------------------------------------------------------------
// AV: x = (E @ V) * inv from unnormalized E planes; heavy-first 1D grid.
// ---------------------------------------------------------------------------
__global__ __launch_bounds__(256) void av_mma_kernel(
    const __nv_bfloat16* __restrict__ eh, const __nv_bfloat16* __restrict__ el,
    const __nv_bfloat16* __restrict__ vth, const __nv_bfloat16* __restrict__ vtl,
    const float* __restrict__ ginv,
    __nv_bfloat16* __restrict__ xh, __nv_bfloat16* __restrict__ xl)
{
    const int t = blockIdx.x;              // 0..511, heavy bm first
    const int bm = 15 - (t >> 5);
    const int bh = t & 31;
    extern __shared__ char dsm[];
    const uint32_t sbase = smem_u32(dsm);
    const int b = bh / HH, h = bh % HH;
    const int tid  = threadIdx.x;
    const int lane = tid & 31;
    const int wid  = tid >> 5;
    const int wm   = wid >> 2;
    const int wn   = wid & 3;

    const size_t aoff = (size_t)bh * SS * SS + (size_t)(bm * 128) * SS;
    const size_t boff = (size_t)bh * DK * SS;

    MmaB16v2 core;
    core.run(sbase, eh + aoff, el + aoff, SS, vth + boff, vtl + boff, SS,
             (bm + 1) * 8, tid);

    #pragma unroll
    for (int mt = 0; mt < 4; mt++) {
        const int row = bm * 128 + wm * 64 + mt * 16 + (lane >> 2);
        const float inv0 = ginv[(size_t)bh * SS + row];
        const float inv1 = ginv[(size_t)bh * SS + row + 8];
        #pragma unroll
        for (int nt = 0; nt < 4; nt++) {
            const int col = wn * 32 + nt * 8 + (lane & 3) * 2;
            const float v0 = core.acc[mt][nt][0] * inv0;
            const float v1 = core.acc[mt][nt][1] * inv0;
            const float v2 = core.acc[mt][nt][2] * inv1;
            const float v3 = core.acc[mt][nt][3] * inv1;
            __nv_bfloat16 h0 = __float2bfloat16_rn(v0);
            __nv_bfloat16 h1 = __float2bfloat16_rn(v1);
            __nv_bfloat16 h2 = __float2bfloat16_rn(v2);
            __nv_bfloat16 h3 = __float2bfloat16_rn(v3);
            const size_t o0 = (size_t)(b * SS + row) * DD + h * DK + col;
            const size_t o1 = (size_t)(b * SS + row + 8) * DD + h * DK + col;
            *(uint32_t*)(xh + o0) = pack_bf2(h0, h1);
            *(uint32_t*)(xl + o0) = pack_bf2(
                __float2bfloat16_rn(v0 - __bfloat162float(h0)),
                __float2bfloat16_rn(v1 - __bfloat162float(h1)));
            *(uint32_t*)(xh + o1) = pack_bf2(h2, h3);
            *(uint32_t*)(xl + o1) = pack_bf2(
                __float2bfloat16_rn(v2 - __bfloat162float(h2)),
                __float2bfloat16_rn(v3 - __bfloat162float(h3)));
        }
    }
}

// ---------------------------------------------------------------------------
extern "C" void kernel_launch(void* const* d_in, const int* in_sizes, int n_in,
                              void* d_out, int out_size)
{
    const float* query = (const float*)d_in[0];
    const float* key   = (const float*)d_in[1];
    const float* value = (const float*)d_in[2];
    const float* Wq = (const float*)d_in[3];
    const float* bq = (const float*)d_in[4];
    const float* Wk = (const float*)d_in[5];
    const float* bk = (const float*)d_in[6];
    const float* Wv = (const float*)d_in[7];
    const float* bv = (const float*)d_in[8];
    const float* Wo = (const float*)d_in[9];
    const float* bo = (const float*)d_in[10];

    float* out  = (float*)d_out;                       // [4096, 2048]
    float* attn = out + (size_t)MTOK * DD;             // [32, 2048, 2048]

    float *v, *rpart, *ginv;
    __nv_bfloat16 *qih, *qil, *kih, *kil, *vih, *vil, *wh, *wl;
    __nv_bfloat16 *qh, *ql, *kh, *kl, *xh, *xl, *vth, *vtl, *eh, *el;
    cudaGetSymbolAddress((void**)&v, g_v);
    cudaGetSymbolAddress((void**)&rpart, g_rpart);
    cudaGetSymbolAddress((void**)&ginv, g_inv);
    cudaGetSymbolAddress((void**)&qih, g_qih);
    cudaGetSymbolAddress((void**)&qil, g_qil);
    cudaGetSymbolAddress((void**)&kih, g_kih);
    cudaGetSymbolAddress((void**)&kil, g_kil);
    cudaGetSymbolAddress((void**)&vih, g_vih);
    cudaGetSymbolAddress((void**)&vil, g_vil);
    cudaGetSymbolAddress((void**)&wh, g_wh);
    cudaGetSymbolAddress((void**)&wl, g_wl);
    cudaGetSymbolAddress((void**)&qh, g_qh);
    cudaGetSymbolAddress((void**)&ql, g_ql);
    cudaGetSymbolAddress((void**)&kh, g_kh);
    cudaGetSymbolAddress((void**)&kl, g_kl);
    cudaGetSymbolAddress((void**)&xh, g_xh);
    cudaGetSymbolAddress((void**)&xl, g_xl);
    cudaGetSymbolAddress((void**)&vth, g_vth);
    cudaGetSymbolAddress((void**)&vtl, g_vtl);
    cudaGetSymbolAddress((void**)&eh, g_eh);
    cudaGetSymbolAddress((void**)&el, g_el);

    static bool attrs_set = false;
    if (!attrs_set) {
        cudaFuncSetAttribute(proj_qkv,
            cudaFuncAttributeMaxDynamicSharedMemorySize, DSMEM_TOTAL);
        cudaFuncSetAttribute(gemm_b16,
            cudaFuncAttributeMaxDynamicSharedMemorySize, DSMEM_TOTAL);
        cudaFuncSetAttribute(scores_exp_kernel,
            cudaFuncAttributeMaxDynamicSharedMemorySize, DSMEM_TOTAL);
        cudaFuncSetAttribute(av_mma_kernel,
            cudaFuncAttributeMaxDynamicSharedMemorySize, DSMEM_TOTAL);
        attrs_set = true;
    }

    // 1. Split inputs and weights into bf16 planes
    dim3 gsi((MTOK * DD) / (256 * 4), 3);
    split_inputs<<<gsi, 256>>>(query, key, value,
                               qih, qil, kih, kil, vih, vil);
    dim3 gsw((DD * DD) / (256 * 4), 4);
    split_weights<<<gsw, 256>>>(Wq, Wk, Wv, Wo, wh, wl);

    // 2. Batched Q/K/V projections
    dim3 gproj(DD / 128, MTOK / 128, 3);
    proj_qkv<<<gproj, 256, DSMEM_TOTAL>>>(
        qih, qil, kih, kil, vih, vil, wh, wl, bq, bk, bv,
        qh, ql, kh, kl, v);

    // 3. V transpose -> planes
    dim3 gtr(SS / 32, DK / 32, BB * HH);
    transpose_v<<<gtr, 256>>>(v, vth, vtl);

    // 4. Scores + exp -> E planes + partials (triangular grid)
    dim3 gsc(136, BB * HH);
    scores_exp_kernel<<<gsc, 256, DSMEM_TOTAL>>>(qh, ql, kh, kl, eh, el, rpart);

    // 5. Finalize attn (fp32 full rows) + inv
    finalize_attn<<<BB * HH * SS, 256>>>(eh, el, rpart, attn, ginv);

    // 6. AV from E planes, scaled by inv (heavy-first)
    av_mma_kernel<<<512, 256, DSMEM_TOTAL>>>(eh, el, vth, vtl, ginv, xh, xl);

    // 7. Output projection
    dim3 gout(DD / 128, MTOK / 128);
    gemm_b16<<<gout, 256, DSMEM_TOTAL>>>(
        xh, xl, wh + (size_t)3 * DD * DD, wl + (size_t)3 * DD * DD, bo, out);
}

// round 9
// speedup vs baseline: 2.5973x; 1.0273x over previous
#include <cuda_runtime.h>
#include <cuda_bf16.h>
#include <cstdint>
#include <math.h>

// ---------------------------------------------------------------------------
// Problem constants
// ---------------------------------------------------------------------------
#define BB   2
#define SS   2048
#define DD   2048
#define HH   16
#define DK   128
#define MTOK (BB * SS)          // 4096 tokens
#define SCALE 0.08838834764831845f  // 1/sqrt(128)

// Scratch (device globals; no cudaMalloc allowed)
static __device__ float g_v [(size_t)MTOK * DD];
static __device__ float g_rpart[(size_t)BB * HH * SS * 16];
static __device__ float g_inv[(size_t)BB * HH * SS];
// bf16 hi/lo planes
static __device__ __nv_bfloat16 g_qih[(size_t)MTOK * DD], g_qil[(size_t)MTOK * DD];
static __device__ __nv_bfloat16 g_kih[(size_t)MTOK * DD], g_kil[(size_t)MTOK * DD];
static __device__ __nv_bfloat16 g_vih[(size_t)MTOK * DD], g_vil[(size_t)MTOK * DD];
static __device__ __nv_bfloat16 g_wh[(size_t)4 * DD * DD], g_wl[(size_t)4 * DD * DD];
static __device__ __nv_bfloat16 g_qh[(size_t)MTOK * DD], g_ql[(size_t)MTOK * DD];
static __device__ __nv_bfloat16 g_kh[(size_t)MTOK * DD], g_kl[(size_t)MTOK * DD];
static __device__ __nv_bfloat16 g_xh[(size_t)MTOK * DD], g_xl[(size_t)MTOK * DD];
static __device__ __nv_bfloat16 g_vth[(size_t)BB * HH * DK * SS];
static __device__ __nv_bfloat16 g_vtl[(size_t)BB * HH * DK * SS];
// Unnormalized-E planes
static __device__ __nv_bfloat16 g_eh[(size_t)BB * HH * SS * SS];
static __device__ __nv_bfloat16 g_el[(size_t)BB * HH * SS * SS];

// ---------------------------------------------------------------------------
// PTX helpers
// ---------------------------------------------------------------------------
#define LDSM_X4(r0, r1, r2, r3, addr) \
    asm volatile("ldmatrix.sync.aligned.m8n8.x4.shared.b16 {%0,%1,%2,%3}, [%4];" \
        : "=r"(r0), "=r"(r1), "=r"(r2), "=r"(r3) : "r"(addr))

#define MMA16816(c, a0, a1, a2, a3, b0, b1) \
    asm volatile("mma.sync.aligned.m16n8k16.row.col.f32.bf16.bf16.f32 " \
        "{%0,%1,%2,%3}, {%4,%5,%6,%7}, {%8,%9}, {%0,%1,%2,%3};" \
        : "+f"((c)[0]), "+f"((c)[1]), "+f"((c)[2]), "+f"((c)[3]) \
        : "r"(a0), "r"(a1), "r"(a2), "r"(a3), "r"(b0), "r"(b1))

#define CP16(dst, src) \
    asm volatile("cp.async.cg.shared.global [%0], [%1], 16;" \
        :: "r"(dst), "l"(src))
#define CPCOMMIT() asm volatile("cp.async.commit_group;" ::: "memory")
#define CPWAIT2()  asm volatile("cp.async.wait_group 2;" ::: "memory")

__device__ __forceinline__ uint32_t smem_u32(const void* p) {
    uint32_t a;
    asm("{ .reg .u64 t; cvta.to.shared.u64 t, %1; cvt.u32.u64 %0, t; }"
        : "=r"(a) : "l"(p));
    return a;
}

__device__ __forceinline__ uint32_t pack_bf2(__nv_bfloat16 a, __nv_bfloat16 b) {
    return (uint32_t)__bfloat16_as_ushort(a) |
           ((uint32_t)__bfloat16_as_ushort(b) << 16);
}

__device__ __forceinline__ void split4(const float4 f, uint2& hi, uint2& lo) {
    __nv_bfloat16 h0 = __float2bfloat16_rn(f.x);
    __nv_bfloat16 h1 = __float2bfloat16_rn(f.y);
    __nv_bfloat16 h2 = __float2bfloat16_rn(f.z);
    __nv_bfloat16 h3 = __float2bfloat16_rn(f.w);
    __nv_bfloat16 l0 = __float2bfloat16_rn(f.x - __bfloat162float(h0));
    __nv_bfloat16 l1 = __float2bfloat16_rn(f.y - __bfloat162float(h1));
    __nv_bfloat16 l2 = __float2bfloat16_rn(f.z - __bfloat162float(h2));
    __nv_bfloat16 l3 = __float2bfloat16_rn(f.w - __bfloat162float(h3));
    hi.x = pack_bf2(h0, h1); hi.y = pack_bf2(h2, h3);
    lo.x = pack_bf2(l0, l1); lo.y = pack_bf2(l2, l3);
}

// ---------------------------------------------------------------------------
// MmaB16v2: 128x128 tile, K-chunk 16, 4-stage cp.async pipeline.
// ---------------------------------------------------------------------------
#define NS 4
#define RS2 48
#define ST_AHI 0
#define ST_ALO 6144
#define ST_BHI 12288
#define ST_BLO 18432
#define ST_BYTES 24576
#define DSMEM_TOTAL (NS * ST_BYTES)   // 98304

struct MmaB16v2 {
    float acc[4][4][4];

    __device__ __forceinline__ static void issue(
        uint32_t sb,
        const __nv_bfloat16* Ah, const __nv_bfloat16* Al, size_t sA,
        const __nv_bfloat16* Bh, const __nv_bfloat16* Bl, size_t sB,
        int k0, int tid)
    {
        const int row  = tid >> 1;
        const int half = tid & 1;
        const uint32_t so = (uint32_t)row * RS2 + half * 16;
        const size_t oA = (size_t)row * sA + k0 + half * 8;
        const size_t oB = (size_t)row * sB + k0 + half * 8;
        CP16(sb + ST_AHI + so, Ah + oA);
        CP16(sb + ST_ALO + so, Al + oA);
        CP16(sb + ST_BHI + so, Bh + oB);
        CP16(sb + ST_BLO + so, Bl + oB);
    }

    __device__ __forceinline__ void run(
        uint32_t sbase,
        const __nv_bfloat16* Ah, const __nv_bfloat16* Al, size_t sA,
        const __nv_bfloat16* Bh, const __nv_bfloat16* Bl, size_t sB,
        const int nIter, const int tid)
    {
        const int lane = tid & 31;
        const int wid  = tid >> 5;
        const int wm   = wid >> 2;
        const int wn   = wid & 3;

        #pragma unroll
        for (int i = 0; i < 4; i++)
            #pragma unroll
            for (int j = 0; j < 4; j++)
                #pragma unroll
                for (int c = 0; c < 4; c++) acc[i][j][c] = 0.0f;

        const uint32_t aAddr = sbase + ST_AHI
            + (uint32_t)(wm * 64 + (lane & 15)) * RS2 + (lane >> 4) * 16;
        const uint32_t bAddr = sbase + ST_BHI
            + (uint32_t)(wn * 32 + (lane & 7) + ((lane >> 4) & 1) * 8) * RS2
            + ((lane >> 3) & 1) * 16;

        #pragma unroll
        for (int p = 0; p < NS - 1; p++) {
            if (p < nIter)
                issue(sbase + p * ST_BYTES, Ah, Al, sA, Bh, Bl, sB, p * 16, tid);
            CPCOMMIT();
        }

        for (int s = 0; s < nIter; s++) {
            CPWAIT2();
            __syncthreads();

            const uint32_t bo = (uint32_t)(s & (NS - 1)) * ST_BYTES;
            uint32_t ahi[4][4], alo[4][4];
            uint32_t bhi[2][4], blo[2][4];
            #pragma unroll
            for (int mt = 0; mt < 4; mt++) {
                const uint32_t a = aAddr + bo + mt * (16 * RS2);
                LDSM_X4(ahi[mt][0], ahi[mt][1], ahi[mt][2], ahi[mt][3], a);
                LDSM_X4(alo[mt][0], alo[mt][1], alo[mt][2], alo[mt][3],
                        a + (ST_ALO - ST_AHI));
            }
            #pragma unroll
            for (int pp = 0; pp < 2; pp++) {
                const uint32_t b = bAddr + bo + pp * (16 * RS2);
                LDSM_X4(bhi[pp][0], bhi[pp][1], bhi[pp][2], bhi[pp][3], b);
                LDSM_X4(blo[pp][0], blo[pp][1], blo[pp][2], blo[pp][3],
                        b + (ST_BLO - ST_BHI));
            }
            #pragma unroll
            for (int mt = 0; mt < 4; mt++) {
                #pragma unroll
                for (int pp = 0; pp < 2; pp++) {
                    #pragma unroll
                    for (int t = 0; t < 2; t++) {
                        const int nt = pp * 2 + t;
                        MMA16816(acc[mt][nt],
                                 ahi[mt][0], ahi[mt][1], ahi[mt][2], ahi[mt][3],
                                 bhi[pp][t * 2], bhi[pp][t * 2 + 1]);
                        MMA16816(acc[mt][nt],
                                 ahi[mt][0], ahi[mt][1], ahi[mt][2], ahi[mt][3],
                                 blo[pp][t * 2], blo[pp][t * 2 + 1]);
                        MMA16816(acc[mt][nt],
                                 alo[mt][0], alo[mt][1], alo[mt][2], alo[mt][3],
                                 bhi[pp][t * 2], bhi[pp][t * 2 + 1]);
                    }
                }
            }

            const int nx = s + NS - 1;
            if (nx < nIter)
                issue(sbase + (uint32_t)(nx & (NS - 1)) * ST_BYTES,
                      Ah, Al, sA, Bh, Bl, sB, nx * 16, tid);
            CPCOMMIT();
        }
        __syncthreads();
    }
};

// ---------------------------------------------------------------------------
// Split fp32 tensors into bf16 hi/lo planes
// ---------------------------------------------------------------------------
__global__ __launch_bounds__(256) void split_inputs(
    const float* __restrict__ a0, const float* __restrict__ a1,
    const float* __restrict__ a2,
    __nv_bfloat16* __restrict__ h0, __nv_bfloat16* __restrict__ l0,
    __nv_bfloat16* __restrict__ h1, __nv_bfloat16* __restrict__ l1,
    __nv_bfloat16* __restrict__ h2, __nv_bfloat16* __restrict__ l2)
{
    const int z = blockIdx.y;
    const float* s = (z == 0) ? a0 : (z == 1) ? a1 : a2;
    __nv_bfloat16* H = (z == 0) ? h0 : (z == 1) ? h1 : h2;
    __nv_bfloat16* L = (z == 0) ? l0 : (z == 1) ? l1 : l2;
    const size_t i = ((size_t)blockIdx.x * 256 + threadIdx.x) * 4;
    float4 f = *(const float4*)(s + i);
    uint2 hi, lo;
    split4(f, hi, lo);
    *(uint2*)(H + i) = hi;
    *(uint2*)(L + i) = lo;
}

__global__ __launch_bounds__(256) void split_weights(
    const float* __restrict__ w0, const float* __restrict__ w1,
    const float* __restrict__ w2, const float* __restrict__ w3,
    __nv_bfloat16* __restrict__ wh, __nv_bfloat16* __restrict__ wl)
{
    const int z = blockIdx.y;
    const float* s = (z == 0) ? w0 : (z == 1) ? w1 : (z == 2) ? w2 : w3;
    const size_t base = (size_t)z * DD * DD;
    const size_t i = ((size_t)blockIdx.x * 256 + threadIdx.x) * 4;
    float4 f = *(const float4*)(s + i);
    uint2 hi, lo;
    split4(f, hi, lo);
    *(uint2*)(wh + base + i) = hi;
    *(uint2*)(wl + base + i) = lo;
}

// ---------------------------------------------------------------------------
// Batched Q/K/V projection: z=0 -> q planes, z=1 -> k planes, z=2 -> v fp32
// ---------------------------------------------------------------------------
__global__ __launch_bounds__(256) void proj_qkv(
    const __nv_bfloat16* __restrict__ qih, const __nv_bfloat16* __restrict__ qil,
    const __nv_bfloat16* __restrict__ kih, const __nv_bfloat16* __restrict__ kil,
    const __nv_bfloat16* __restrict__ vih, const __nv_bfloat16* __restrict__ vil,
    const __nv_bfloat16* __restrict__ wh, const __nv_bfloat16* __restrict__ wl,
    const float* __restrict__ bq, const float* __restrict__ bk,
    const float* __restrict__ bv,
    __nv_bfloat16* __restrict__ qh, __nv_bfloat16* __restrict__ ql,
    __nv_bfloat16* __restrict__ kh, __nv_bfloat16* __restrict__ kl,
    float* __restrict__ v)
{
    extern __shared__ char dsm[];
    const uint32_t sbase = smem_u32(dsm);
    const int tid  = threadIdx.x;
    const int lane = tid & 31;
    const int wid  = tid >> 5;
    const int wm   = wid >> 2;
    const int wn   = wid & 3;
    const int bn   = blockIdx.x;
    const int bm   = blockIdx.y;
    const int z    = blockIdx.z;

    const __nv_bfloat16* Ah = (z == 0) ? qih : (z == 1) ? kih : vih;
    const __nv_bfloat16* Al = (z == 0) ? qil : (z == 1) ? kil : vil;
    const float* bias = (z == 0) ? bq : (z == 1) ? bk : bv;
    const size_t wbase = (size_t)z * DD * DD;

    MmaB16v2 core;
    core.run(sbase,
             Ah + (size_t)(bm * 128) * DD, Al + (size_t)(bm * 128) * DD, DD,
             wh + wbase + (size_t)(bn * 128) * DD,
             wl + wbase + (size_t)(bn * 128) * DD, DD,
             DD / 16, tid);

    #pragma unroll
    for (int mt = 0; mt < 4; mt++) {
        const int row = bm * 128 + wm * 64 + mt * 16 + (lane >> 2);
        #pragma unroll
        for (int nt = 0; nt < 4; nt++) {
            const int col = bn * 128 + wn * 32 + nt * 8 + (lane & 3) * 2;
            const float b0 = bias[col], b1 = bias[col + 1];
            const float v0 = core.acc[mt][nt][0] + b0;
            const float v1 = core.acc[mt][nt][1] + b1;
            const float v2 = core.acc[mt][nt][2] + b0;
            const float v3 = core.acc[mt][nt][3] + b1;
            if (z == 2) {
                *(float2*)(v + (size_t)row * DD + col) = make_float2(v0, v1);
                *(float2*)(v + (size_t)(row + 8) * DD + col) = make_float2(v2, v3);
            } else {
                __nv_bfloat16* H = (z == 0) ? qh : kh;
                __nv_bfloat16* L = (z == 0) ? ql : kl;
                __nv_bfloat16 h0 = __float2bfloat16_rn(v0);
                __nv_bfloat16 h1 = __float2bfloat16_rn(v1);
                __nv_bfloat16 h2 = __float2bfloat16_rn(v2);
                __nv_bfloat16 h3 = __float2bfloat16_rn(v3);
                *(uint32_t*)(H + (size_t)row * DD + col) = pack_bf2(h0, h1);
                *(uint32_t*)(L + (size_t)row * DD + col) = pack_bf2(
                    __float2bfloat16_rn(v0 - __bfloat162float(h0)),
                    __float2bfloat16_rn(v1 - __bfloat162float(h1)));
                *(uint32_t*)(H + (size_t)(row + 8) * DD + col) = pack_bf2(h2, h3);
                *(uint32_t*)(L + (size_t)(row + 8) * DD + col) = pack_bf2(
                    __float2bfloat16_rn(v2 - __bfloat162float(h2)),
                    __float2bfloat16_rn(v3 - __bfloat162float(h3)));
            }
        }
    }
}

// ---------------------------------------------------------------------------
// Final GEMM: out = x @ Wo^T + bo
// ---------------------------------------------------------------------------
__global__ __launch_bounds__(256) void gemm_b16(
    const __nv_bfloat16* __restrict__ Ah, const __nv_bfloat16* __restrict__ Al,
    const __nv_bfloat16* __restrict__ Wh, const __nv_bfloat16* __restrict__ Wl,
    const float* __restrict__ bias, float* __restrict__ C)
{
    extern __shared__ char dsm[];
    const uint32_t sbase = smem_u32(dsm);
    const int tid  = threadIdx.x;
    const int lane = tid & 31;
    const int wid  = tid >> 5;
    const int wm   = wid >> 2;
    const int wn   = wid & 3;
    const int bn   = blockIdx.x;
    const int bm   = blockIdx.y;

    MmaB16v2 core;
    core.run(sbase,
             Ah + (size_t)(bm * 128) * DD, Al + (size_t)(bm * 128) * DD, DD,
             Wh + (size_t)(bn * 128) * DD, Wl + (size_t)(bn * 128) * DD, DD,
             DD / 16, tid);

    #pragma unroll
    for (int mt = 0; mt < 4; mt++) {
        const int row = bm * 128 + wm * 64 + mt * 16 + (lane >> 2);
        #pragma unroll
        for (int nt = 0; nt < 4; nt++) {
            const int col = bn * 128 + wn * 32 + nt * 8 + (lane & 3) * 2;
            const float b0 = bias[col], b1 = bias[col + 1];
            float2 o0, o1;
            o0.x = core.acc[mt][nt][0] + b0; o0.y = core.acc[mt][nt][1] + b1;
            o1.x = core.acc[mt][nt][2] + b0; o1.y = core.acc[mt][nt][3] + b1;
            *(float2*)(C + (size_t)row * DD + col) = o0;
            *(float2*)(C + (size_t)(row + 8) * DD + col) = o1;
        }
    }
}

// ---------------------------------------------------------------------------
// Scores+exp: triangular grid (136 lower tiles per bh). Writes unnormalized
// E planes (bf16 hi/lo) + per-tile row-sum partials.
// ---------------------------------------------------------------------------
__global__ __launch_bounds__(256) void scores_exp_kernel(
    const __nv_bfloat16* __restrict__ qh, const __nv_bfloat16* __restrict__ ql,
    const __nv_bfloat16* __restrict__ kh, const __nv_bfloat16* __restrict__ kl,
    __nv_bfloat16* __restrict__ eh, __nv_bfloat16* __restrict__ el,
    float* __restrict__ rpart)
{
    const int idx = blockIdx.x;            // 0..135 (lower-triangle tile id)
    int bm = (int)((sqrtf(8.f * idx + 1.f) - 1.f) * 0.5f);
    while ((bm + 1) * (bm + 2) / 2 <= idx) bm++;
    while (bm * (bm + 1) / 2 > idx) bm--;
    const int bn = idx - bm * (bm + 1) / 2;
    const int bh = blockIdx.y;
    const int tid = threadIdx.x;

    extern __shared__ char dsm[];
    __shared__ float rs[128][4];
    const uint32_t sbase = smem_u32(dsm);
    const int lane = tid & 31;
    const int wid  = tid >> 5;
    const int wm   = wid >> 2;
    const int wn   = wid & 3;
    const int b = bh / HH, h = bh % HH;

    const size_t aoff = (size_t)(b * SS + bm * 128) * DD + h * DK;
    const size_t boff = (size_t)(b * SS + bn * 128) * DD + h * DK;

    MmaB16v2 core;
    core.run(sbase, qh + aoff, ql + aoff, DD, kh + boff, kl + boff, DD,
             DK / 16, tid);

    __nv_bfloat16* peh = eh + (size_t)bh * SS * SS;
    __nv_bfloat16* pel = el + (size_t)bh * SS * SS;

    float rsum[4][2];
    #pragma unroll
    for (int mt = 0; mt < 4; mt++) { rsum[mt][0] = 0.f; rsum[mt][1] = 0.f; }

    #pragma unroll
    for (int mt = 0; mt < 4; mt++) {
        const int r0 = bm * 128 + wm * 64 + mt * 16 + (lane >> 2);
        const int r1 = r0 + 8;
        #pragma unroll
        for (int nt = 0; nt < 4; nt++) {
            const int col = bn * 128 + wn * 32 + nt * 8 + (lane & 3) * 2;
            float e0 = (col     <= r0) ? __expf(core.acc[mt][nt][0] * SCALE) : 0.f;
            float e1 = (col + 1 <= r0) ? __expf(core.acc[mt][nt][1] * SCALE) : 0.f;
            float e2 = (col     <= r1) ? __expf(core.acc[mt][nt][2] * SCALE) : 0.f;
            float e3 = (col + 1 <= r1) ? __expf(core.acc[mt][nt][3] * SCALE) : 0.f;
            rsum[mt][0] += e0 + e1;
            rsum[mt][1] += e2 + e3;
            __nv_bfloat16 h0 = __float2bfloat16_rn(e0);
            __nv_bfloat16 h1 = __float2bfloat16_rn(e1);
            __nv_bfloat16 h2 = __float2bfloat16_rn(e2);
            __nv_bfloat16 h3 = __float2bfloat16_rn(e3);
            *(uint32_t*)(peh + (size_t)r0 * SS + col) = pack_bf2(h0, h1);
            *(uint32_t*)(pel + (size_t)r0 * SS + col) = pack_bf2(
                __float2bfloat16_rn(e0 - __bfloat162float(h0)),
                __float2bfloat16_rn(e1 - __bfloat162float(h1)));
            *(uint32_t*)(peh + (size_t)r1 * SS + col) = pack_bf2(h2, h3);
            *(uint32_t*)(pel + (size_t)r1 * SS + col) = pack_bf2(
                __float2bfloat16_rn(e2 - __bfloat162float(h2)),
                __float2bfloat16_rn(e3 - __bfloat162float(h3)));
        }
    }

    #pragma unroll
    for (int mt = 0; mt < 4; mt++) {
        #pragma unroll
        for (int hf = 0; hf < 2; hf++) {
            float vv = rsum[mt][hf];
            vv += __shfl_xor_sync(0xffffffffu, vv, 1);
            vv += __shfl_xor_sync(0xffffffffu, vv, 2);
            if ((lane & 3) == 0) {
                const int lrow = wm * 64 + mt * 16 + hf * 8 + (lane >> 2);
                rs[lrow][wn] = vv;
            }
        }
    }
    __syncthreads();
    if (tid < 128) {
        const float p = rs[tid][0] + rs[tid][1] + rs[tid][2] + rs[tid][3];
        rpart[((size_t)bh * SS + bm * 128 + tid) * 16 + bn] = p;
    }
}

// ---------------------------------------------------------------------------
// ginv: 1/rowsum from partials (tiny; unblocks AV without finalize)
// ---------------------------------------------------------------------------
__global__ __launch_bounds__(256) void ginv_kernel(
    const float* __restrict__ rpart, float* __restrict__ ginv)
{
    const int i = blockIdx.x * 256 + threadIdx.x;   // bh*SS + s
    const int s = i & (SS - 1);
    const float* p = rpart + (size_t)i * 16;
    const int nb = (s >> 7) + 1;
    float sum = 0.f;
    for (int k = 0; k < nb; k++) sum += p[k];
    ginv[i] = 1.0f / sum;
}

// ---------------------------------------------------------------------------
// Zero the above-diagonal tail of attn (side stream, overlapped with proj)
// ---------------------------------------------------------------------------
__global__ __launch_bounds__(256) void zero_tail(float* __restrict__ attn)
{
    const int blk = blockIdx.x;           // bh*SS + s
    const int s   = blk & (SS - 1);
    const int limit = ((s >> 7) + 1) * 128;
    float* row = attn + (size_t)blk * SS;
    const float4 z = make_float4(0.f, 0.f, 0.f, 0.f);
    for (int j = limit + threadIdx.x * 4; j < SS; j += 1024)
        *(float4*)(row + j) = z;
}

// ---------------------------------------------------------------------------
// Finalize (prefix only): attn[0..limit) = (Eh+El)*inv. Tail pre-zeroed.
// ---------------------------------------------------------------------------
__global__ __launch_bounds__(256) void finalize_prefix(
    const __nv_bfloat16* __restrict__ eh, const __nv_bfloat16* __restrict__ el,
    const float* __restrict__ ginv, float* __restrict__ attn)
{
    const int blk = blockIdx.x;           // bh*SS + s
    const int s   = blk & (SS - 1);
    const float inv = ginv[blk];
    const __nv_bfloat16* reh = eh + (size_t)blk * SS;
    const __nv_bfloat16* rel = el + (size_t)blk * SS;
    float* row = attn + (size_t)blk * SS;
    const int limit = ((s >> 7) + 1) * 128;
    for (int j = threadIdx.x * 4; j < limit; j += 1024) {
        const __nv_bfloat162 h2 = *(const __nv_bfloat162*)(reh + j);
        const __nv_bfloat162 h3 = *(const __nv_bfloat162*)(reh + j + 2);
        const __nv_bfloat162 l2 = *(const __nv_bfloat162*)(rel + j);
        const __nv_bfloat162 l3 = *(const __nv_bfloat162*)(rel + j + 2);
        float4 o;
        o.x = (__bfloat162float(h2.x) + __bfloat162float(l2.x)) * inv;
        o.y = (__bfloat162float(h2.y) + __bfloat162float(l2.y)) * inv;
        o.z = (__bfloat162float(h3.x) + __bfloat162float(l3.x)) * inv;
        o.w = (__bfloat162float(h3.y) + __bfloat162float(l3.y)) * inv;
        *(float4*)(row + j) = o;
    }
}

// ---------------------------------------------------------------------------
// Transpose V per head into bf16 hi/lo planes: vt[bh][d][s]
// ---------------------------------------------------------------------------
__global__ __launch_bounds__(256) void transpose_v(
    const float* __restrict__ v,
    __nv_bfloat16* __restrict__ vth, __nv_bfloat16* __restrict__ vtl)
{
    __shared__ float t[32][33];
    const int bh = blockIdx.z, b = bh / HH, h = bh % HH;
    const int s0 = blockIdx.x * 32, d0 = blockIdx.y * 32;
    const int tx = threadIdx.x & 31, ty = threadIdx.x >> 5;
    #pragma unroll
    for (int i = 0; i < 4; i++)
        t[ty + i * 8][tx] =
            v[(size_t)(b * SS + s0 + ty + i * 8) * DD + h * DK + d0 + tx];
    __syncthreads();
    #pragma unroll
    for (int i = 0; i < 4; i++) {
        const float f = t[tx][ty + i * 8];
        const __nv_bfloat16 hh = __float2bfloat16_rn(f);
        const __nv_bfloat16 ll = __float2bfloat16_rn(f - __bfloat162float(hh));
        const size_t idx = (size_t)bh * DK * SS + (size_t)(d0 + ty + i * 8) * SS
                         + s0 + tx;
        vth[idx] = hh;
        vtl[idx] = ll;
    }
}

// ---------------------------------------------------------------------------
// AV: x = (E @ V) * inv from unnormalized E planes; heavy-first 1D grid.
// ---------------------------------------------------------------------------
__global__ __launch_bounds__(256) void av_mma_kernel(
    const __nv_bfloat16* __restrict__ eh, const __nv_bfloat16* __restrict__ el,
    const __nv_bfloat16* __restrict__ vth, const __nv_bfloat16* __restrict__ vtl,
    const float* __restrict__ ginv,
    __nv_bfloat16* __restrict__ xh, __nv_bfloat16* __restrict__ xl)
{
    const int t = blockIdx.x;              // 0..511, heavy bm first
    const int bm = 15 - (t >> 5);
    const int bh = t & 31;
    extern __shared__ char dsm[];
    const uint32_t sbase = smem_u32(dsm);
    const int b = bh / HH, h = bh % HH;
    const int tid  = threadIdx.x;
    const int lane = tid & 31;
    const int wid  = tid >> 5;
    const int wm   = wid >> 2;
    const int wn   = wid & 3;

    const size_t aoff = (size_t)bh * SS * SS + (size_t)(bm * 128) * SS;
    const size_t boff = (size_t)bh * DK * SS;

    MmaB16v2 core;
    core.run(sbase, eh + aoff, el + aoff, SS, vth + boff, vtl + boff, SS,
             (bm + 1) * 8, tid);

    #pragma unroll
    for (int mt = 0; mt < 4; mt++) {
        const int row = bm * 128 + wm * 64 + mt * 16 + (lane >> 2);
        const float inv0 = ginv[(size_t)bh * SS + row];
        const float inv1 = ginv[(size_t)bh * SS + row + 8];
        #pragma unroll
        for (int nt = 0; nt < 4; nt++) {
            const int col = wn * 32 + nt * 8 + (lane & 3) * 2;
            const float v0 = core.acc[mt][nt][0] * inv0;
            const float v1 = core.acc[mt][nt][1] * inv0;
            const float v2 = core.acc[mt][nt][2] * inv1;
            const float v3 = core.acc[mt][nt][3] * inv1;
            __nv_bfloat16 h0 = __float2bfloat16_rn(v0);
            __nv_bfloat16 h1 = __float2bfloat16_rn(v1);
            __nv_bfloat16 h2 = __float2bfloat16_rn(v2);
            __nv_bfloat16 h3 = __float2bfloat16_rn(v3);
            const size_t o0 = (size_t)(b * SS + row) * DD + h * DK + col;
            const size_t o1 = (size_t)(b * SS + row + 8) * DD + h * DK + col;
            *(uint32_t*)(xh + o0) = pack_bf2(h0, h1);
            *(uint32_t*)(xl + o0) = pack_bf2(
                __float2bfloat16_rn(v0 - __bfloat162float(h0)),
                __float2bfloat16_rn(v1 - __bfloat162float(h1)));
            *(uint32_t*)(xh + o1) = pack_bf2(h2, h3);
            *(uint32_t*)(xl + o1) = pack_bf2(
                __float2bfloat16_rn(v2 - __bfloat162float(h2)),
                __float2bfloat16_rn(v3 - __bfloat162float(h3)));
        }
    }
}

// ---------------------------------------------------------------------------
extern "C" void kernel_launch(void* const* d_in, const int* in_sizes, int n_in,
                              void* d_out, int out_size)
{
    const float* query = (const float*)d_in[0];
    const float* key   = (const float*)d_in[1];
    const float* value = (const float*)d_in[2];
    const float* Wq = (const float*)d_in[3];
    const float* bq = (const float*)d_in[4];
    const float* Wk = (const float*)d_in[5];
    const float* bk = (const float*)d_in[6];
    const float* Wv = (const float*)d_in[7];
    const float* bv = (const float*)d_in[8];
    const float* Wo = (const float*)d_in[9];
    const float* bo = (const float*)d_in[10];

    float* out  = (float*)d_out;                       // [4096, 2048]
    float* attn = out + (size_t)MTOK * DD;             // [32, 2048, 2048]

    float *v, *rpart, *ginv;
    __nv_bfloat16 *qih, *qil, *kih, *kil, *vih, *vil, *wh, *wl;
    __nv_bfloat16 *qh, *ql, *kh, *kl, *xh, *xl, *vth, *vtl, *eh, *el;
    cudaGetSymbolAddress((void**)&v, g_v);
    cudaGetSymbolAddress((void**)&rpart, g_rpart);
    cudaGetSymbolAddress((void**)&ginv, g_inv);
    cudaGetSymbolAddress((void**)&qih, g_qih);
    cudaGetSymbolAddress((void**)&qil, g_qil);
    cudaGetSymbolAddress((void**)&kih, g_kih);
    cudaGetSymbolAddress((void**)&kil, g_kil);
    cudaGetSymbolAddress((void**)&vih, g_vih);
    cudaGetSymbolAddress((void**)&vil, g_vil);
    cudaGetSymbolAddress((void**)&wh, g_wh);
    cudaGetSymbolAddress((void**)&wl, g_wl);
    cudaGetSymbolAddress((void**)&qh, g_qh);
    cudaGetSymbolAddress((void**)&ql, g_ql);
    cudaGetSymbolAddress((void**)&kh, g_kh);
    cudaGetSymbolAddress((void**)&kl, g_kl);
    cudaGetSymbolAddress((void**)&xh, g_xh);
    cudaGetSymbolAddress((void**)&xl, g_xl);
    cudaGetSymbolAddress((void**)&vth, g_vth);
    cudaGetSymbolAddress((void**)&vtl, g_vtl);
    cudaGetSymbolAddress((void**)&eh, g_eh);
    cudaGetSymbolAddress((void**)&el, g_el);

    static cudaStream_t s1 = nullptr;
    static cudaEvent_t evA = nullptr, evB = nullptr, evF = nullptr;
    if (s1 == nullptr) {
        cudaStreamCreateWithFlags(&s1, cudaStreamNonBlocking);
        cudaEventCreateWithFlags(&evA, cudaEventDisableTiming);
        cudaEventCreateWithFlags(&evB, cudaEventDisableTiming);
        cudaEventCreateWithFlags(&evF, cudaEventDisableTiming);
        cudaFuncSetAttribute(proj_qkv,
            cudaFuncAttributeMaxDynamicSharedMemorySize, DSMEM_TOTAL);
        cudaFuncSetAttribute(gemm_b16,
            cudaFuncAttributeMaxDynamicSharedMemorySize, DSMEM_TOTAL);
        cudaFuncSetAttribute(scores_exp_kernel,
            cudaFuncAttributeMaxDynamicSharedMemorySize, DSMEM_TOTAL);
        cudaFuncSetAttribute(av_mma_kernel,
            cudaFuncAttributeMaxDynamicSharedMemorySize, DSMEM_TOTAL);
    }

    // Fork side stream: zero the above-diagonal attn tail (no dependencies)
    cudaEventRecord(evA, 0);
    cudaStreamWaitEvent(s1, evA, 0);
    zero_tail<<<BB * HH * SS, 256, 0, s1>>>(attn);

    // Main stream: splits -> proj -> transpose -> scores -> ginv
    dim3 gsi((MTOK * DD) / (256 * 4), 3);
    split_inputs<<<gsi, 256>>>(query, key, value,
                               qih, qil, kih, kil, vih, vil);
    dim3 gsw((DD * DD) / (256 * 4), 4);
    split_weights<<<gsw, 256>>>(Wq, Wk, Wv, Wo, wh, wl);

    dim3 gproj(DD / 128, MTOK / 128, 3);
    proj_qkv<<<gproj, 256, DSMEM_TOTAL>>>(
        qih, qil, kih, kil, vih, vil, wh, wl, bq, bk, bv,
        qh, ql, kh, kl, v);

    dim3 gtr(SS / 32, DK / 32, BB * HH);
    transpose_v<<<gtr, 256>>>(v, vth, vtl);

    dim3 gsc(136, BB * HH);
    scores_exp_kernel<<<gsc, 256, DSMEM_TOTAL>>>(qh, ql, kh, kl, eh, el, rpart);

    ginv_kernel<<<(BB * HH * SS) / 256, 256>>>(rpart, ginv);

    // Side stream: finalize attn prefix (overlaps AV + output projection)
    cudaEventRecord(evB, 0);
    cudaStreamWaitEvent(s1, evB, 0);
    finalize_prefix<<<BB * HH * SS, 256, 0, s1>>>(eh, el, ginv, attn);
    cudaEventRecord(evF, s1);

    // Main stream: AV, output projection
    av_mma_kernel<<<512, 256, DSMEM_TOTAL>>>(eh, el, vth, vtl, ginv, xh, xl);

    dim3 gout(DD / 128, MTOK / 128);
    gemm_b16<<<gout, 256, DSMEM_TOTAL>>>(
        xh, xl, wh + (size_t)3 * DD * DD, wl + (size_t)3 * DD * DD, bo, out);

    // Join side stream into the graph
    cudaStreamWaitEvent(0, evF, 0);
}